// round 13
// baseline (speedup 1.0000x reference)
#include <cuda_runtime.h>
#include <mma.h>
#include <cstdint>

using namespace nvcuda;

constexpr int B   = 256;
constexpr int T   = 256;
constexpr int D   = 72;
constexpr int HID = 512;
constexpr int H   = 1024;
constexpr int H3  = 3 * H;
constexpr int P   = 10;
constexpr int BT  = B * T;

// ----------------------------------------------------------------------------
// Device scratch
// ----------------------------------------------------------------------------
__device__ float g_buf1  [(size_t)BT * HID];
__device__ float g_latent[(size_t)BT * H];
__device__ float g_xp    [(size_t)BT * H3];   // [T, B, 3H]
__device__ float g_eout  [(size_t)BT * H];    // [T, B, H]
__device__ float g_hb0   [B * H];             // hF fragment-order
__device__ float g_hb1   [B * H];
__device__ float g_logits[BT];
__device__ float g_lpart [4 * BT];
__device__ float g_wts   [BT];
__device__ float g_hs    [B * H];
__device__ float g_hs2   [B * H];
__device__ float g_hrow  [B * H];
__device__ float g_p0    [B * D];
__device__ float g_d1    [B * HID];
__device__ float g_dinp  [B * H];
__device__ float g_gi    [B * H3];
__device__ float g_l1    [B * HID];
constexpr int WSW_TILE = 128 * 6 * 64;
__device__ float g_wsw_enc[(size_t)64 * WSW_TILE];
__device__ float g_wsw_dec[(size_t)64 * WSW_TILE];
// tf32-pre-rounded GEMM weights (contiguous in g_wtf, cvt order below)
constexpr size_t WT_P2L1   = 0;
constexpr size_t WT_P2L2   = WT_P2L1 + 512 * 72;
constexpr size_t WT_ENCWIH = WT_P2L2 + 1024 * 512;
constexpr size_t WT_L2S1   = WT_ENCWIH + (size_t)3072 * 1024;
constexpr size_t WT_DECWIH = WT_L2S1 + 512 * 1024;
constexpr size_t WT_L2P1   = WT_DECWIH + (size_t)3072 * 1024;
constexpr size_t WT_TOTAL  = WT_L2P1 + 512 * 1024;
__device__ float g_wtf[WT_TOTAL];
// padded (128 x 512) tf32 l2p_w2 + padded bias for pred-as-GEMM
__device__ float g_wl2p2[128 * 512];
__device__ float g_bl2p2[128];

__device__ __forceinline__ size_t hf_idx(int b, int k) {
    return ((((size_t)(k >> 3) * 16 + (b >> 4)) * 32 +
             ((b & 7) * 4 + (k & 3))) << 2) +
           (((b >> 3) & 1) + 2 * ((k >> 2) & 1));
}

__device__ __forceinline__ float sigf(float x) { return 1.f / (1.f + expf(-x)); }

__device__ __forceinline__ uint32_t f2tf32(float x) {
    uint32_t r;
    asm("cvt.rna.tf32.f32 %0, %1;" : "=r"(r) : "f"(x));
    return r;
}

__device__ __forceinline__ void mma_tf32(float d[4], const uint32_t a[4],
                                         uint32_t b0, uint32_t b1) {
    asm volatile(
        "mma.sync.aligned.m16n8k8.row.col.f32.tf32.tf32.f32 "
        "{%0,%1,%2,%3}, {%4,%5,%6,%7}, {%8,%9}, {%0,%1,%2,%3};"
        : "+f"(d[0]), "+f"(d[1]), "+f"(d[2]), "+f"(d[3])
        : "r"(a[0]), "r"(a[1]), "r"(a[2]), "r"(a[3]), "r"(b0), "r"(b1));
}

__device__ __forceinline__ uint32_t smem_u32(const void* p) {
    return (uint32_t)__cvta_generic_to_shared(p);
}
__device__ __forceinline__ void cp16(uint32_t dst, const void* src) {
    asm volatile("cp.async.ca.shared.global [%0], [%1], 16;" :: "r"(dst), "l"(src));
}

// ----------------------------------------------------------------------------
// One merged tf32 weight-rounding kernel (6 segments -> contiguous g_wtf)
// ----------------------------------------------------------------------------
constexpr int CN0 = 512 * 72 / 4;
constexpr int CN1 = CN0 + 1024 * 512 / 4;
constexpr int CN2 = CN1 + 3072 * 1024 / 4;
constexpr int CN3 = CN2 + 512 * 1024 / 4;
constexpr int CN4 = CN3 + 3072 * 1024 / 4;
constexpr int CN5 = CN4 + 512 * 1024 / 4;      // total float4s

__global__ void cvt_all(const float* __restrict__ s0, const float* __restrict__ s1,
                        const float* __restrict__ s2, const float* __restrict__ s3,
                        const float* __restrict__ s4, const float* __restrict__ s5,
                        float* __restrict__ dst)
{
    int i = blockIdx.x * blockDim.x + threadIdx.x;
    if (i >= CN5) return;
    const float* src; int off;
    if      (i < CN0) { src = s0; off = i; }
    else if (i < CN1) { src = s1; off = i - CN0; }
    else if (i < CN2) { src = s2; off = i - CN1; }
    else if (i < CN3) { src = s3; off = i - CN2; }
    else if (i < CN4) { src = s4; off = i - CN3; }
    else              { src = s5; off = i - CN4; }
    float4 v = reinterpret_cast<const float4*>(src)[off];
    v.x = __uint_as_float(f2tf32(v.x));
    v.y = __uint_as_float(f2tf32(v.y));
    v.z = __uint_as_float(f2tf32(v.z));
    v.w = __uint_as_float(f2tf32(v.w));
    reinterpret_cast<float4*>(dst)[i] = v;
}

// pad l2p_w2 (72x512) -> g_wl2p2 (128x512 tf32, zero rows 72..127), bias pad
__global__ void pad_l2p2(const float* __restrict__ w2, const float* __restrict__ b2,
                         float* __restrict__ wp, float* __restrict__ bp)
{
    int i = blockIdx.x * blockDim.x + threadIdx.x;
    if (i < 128 * 512) {
        int r = i / 512;
        wp[i] = (r < D) ? __uint_as_float(f2tf32(w2[(size_t)r * 512 + (i % 512)])) : 0.f;
    }
    if (i < 128) bp[i] = (i < D) ? b2[i] : 0.f;
}

// ----------------------------------------------------------------------------
// GEMM v3 (128x128, 256 thr, 3-stage cp.async) + nstore mask + fused logits
// ----------------------------------------------------------------------------
#define BM 128
#define BN 128
#define BK 32
constexpr int GLDS = BK + 4;
constexpr int STG  = (BM + BN) * GLDS;
constexpr int GM_SMEM_BYTES = 3 * STG * 4;

__device__ __forceinline__ void cp_stage(
    float* st, const float* __restrict__ A, int lda,
    const float* __restrict__ W, int K,
    int bm, int bn, int kk, int tid)
{
#pragma unroll
    for (int i = 0; i < 4; i++) {
        int idx = tid + i * 256;
        int r   = idx >> 3;
        int c4  = (idx & 7) * 4;
        int gk  = kk + c4;
        float* da = st + r * GLDS + c4;
        float* db = st + (BM + r) * GLDS + c4;
        const float* sa = A + (size_t)(bm + r) * lda + gk;
        const float* sb = W + (size_t)(bn + r) * K + gk;
        if (gk + 4 <= K) {
            cp16(smem_u32(da), sa);
            cp16(smem_u32(db), sb);
        } else {
            float4 va, vb;
            va.x = (gk + 0 < K) ? sa[0] : 0.f;  vb.x = (gk + 0 < K) ? sb[0] : 0.f;
            va.y = (gk + 1 < K) ? sa[1] : 0.f;  vb.y = (gk + 1 < K) ? sb[1] : 0.f;
            va.z = (gk + 2 < K) ? sa[2] : 0.f;  vb.z = (gk + 2 < K) ? sb[2] : 0.f;
            va.w = (gk + 3 < K) ? sa[3] : 0.f;  vb.w = (gk + 3 < K) ? sb[3] : 0.f;
            *reinterpret_cast<float4*>(da) = va;
            *reinterpret_cast<float4*>(db) = vb;
        }
    }
    asm volatile("cp.async.commit_group;");
}

__global__ void __launch_bounds__(256, 2)
gemm_tf32_v3(const float* __restrict__ A, int lda,
             const float* __restrict__ W,
             const float* __restrict__ bias,
             float* __restrict__ C, int ldc,
             int M, int N, int K, int act, int permute_bt, int nstore,
             const float* __restrict__ lw, float* __restrict__ lpart)
{
    extern __shared__ float sm[];
    float* Cs = sm;

    const int bm  = blockIdx.y * BM;
    const int bn  = blockIdx.x * BN;
    const int tid = threadIdx.x;
    const int w   = tid >> 5;
    const int wm  = w & 3;
    const int wn  = w >> 2;

    wmma::fragment<wmma::accumulator, 16, 16, 8, float> c[2][4];
#pragma unroll
    for (int i = 0; i < 2; i++)
#pragma unroll
        for (int j = 0; j < 4; j++)
            wmma::fill_fragment(c[i][j], 0.0f);

    const int niter = (K + BK - 1) / BK;

    cp_stage(sm, A, lda, W, K, bm, bn, 0, tid);
    if (niter > 1) cp_stage(sm + STG, A, lda, W, K, bm, bn, BK, tid);

    for (int it = 0; it < niter; it++) {
        if (it + 1 < niter) asm volatile("cp.async.wait_group 1;");
        else                asm volatile("cp.async.wait_group 0;");
        __syncthreads();
        if (it + 2 < niter)
            cp_stage(sm + ((it + 2) % 3) * STG, A, lda, W, K, bm, bn,
                     (it + 2) * BK, tid);

        const float* As = sm + (it % 3) * STG;
        const float* Bs = As + BM * GLDS;
#pragma unroll
        for (int ks = 0; ks < 4; ks++) {
            wmma::fragment<wmma::matrix_a, 16, 16, 8, wmma::precision::tf32, wmma::row_major> af[2];
            wmma::fragment<wmma::matrix_b, 16, 16, 8, wmma::precision::tf32, wmma::col_major> bf[4];
#pragma unroll
            for (int i = 0; i < 2; i++) {
                wmma::load_matrix_sync(af[i], As + (wm * 32 + i * 16) * GLDS + ks * 8, GLDS);
#pragma unroll
                for (int e = 0; e < af[i].num_elements; e++)
                    af[i].x[e] = wmma::__float_to_tf32(af[i].x[e]);
            }
#pragma unroll
            for (int j = 0; j < 4; j++)
                wmma::load_matrix_sync(bf[j], Bs + (wn * 64 + j * 16) * GLDS + ks * 8, GLDS);
#pragma unroll
            for (int i = 0; i < 2; i++)
#pragma unroll
                for (int j = 0; j < 4; j++)
                    wmma::mma_sync(c[i][j], af[i], bf[j], c[i][j]);
        }
    }

    __syncthreads();
#pragma unroll
    for (int i = 0; i < 2; i++)
#pragma unroll
        for (int j = 0; j < 4; j++)
            wmma::store_matrix_sync(Cs + (wm * 32 + i * 16) * (BN + 4) + wn * 64 + j * 16,
                                    c[i][j], BN + 4, wmma::mem_row_major);
    __syncthreads();

#pragma unroll
    for (int i = 0; i < 16; i++) {
        int idx4 = tid + i * 256;
        int r    = idx4 >> 5;
        int c4   = (idx4 & 31) * 4;
        float4 v = *reinterpret_cast<const float4*>(Cs + r * (BN + 4) + c4);
        if (bias) {
            float4 bv = *reinterpret_cast<const float4*>(bias + bn + c4);
            v.x += bv.x; v.y += bv.y; v.z += bv.z; v.w += bv.w;
        }
        if (act == 1) {
            v.x = fmaxf(v.x, 0.f); v.y = fmaxf(v.y, 0.f);
            v.z = fmaxf(v.z, 0.f); v.w = fmaxf(v.w, 0.f);
        }
        int gr   = bm + r;
        int orow = permute_bt ? (((gr & 255) << 8) | (gr >> 8)) : gr;
        if (!lpart) {
            if (bn + c4 < nstore)
                *reinterpret_cast<float4*>(C + (size_t)orow * ldc + bn + c4) = v;
        } else {
            float4 wv4 = *reinterpret_cast<const float4*>(lw + bn + c4);
            float d = v.x * wv4.x + v.y * wv4.y + v.z * wv4.z + v.w * wv4.w;
#pragma unroll
            for (int o = 16; o > 0; o >>= 1)
                d += __shfl_xor_sync(0xffffffffu, d, o);
            if ((tid & 31) == 0)
                lpart[(size_t)(bn >> 7) * M + orow] = d;
        }
    }
}

// ----------------------------------------------------------------------------
// GEMM v4: 128x256 tile, 512 threads (4m x 4n warps), 3-stage cp.async.
// For large-N GEMMs (N % 256 == 0). K must be multiple of 4.
// ----------------------------------------------------------------------------
#define V4BN 256
constexpr int STG4 = (BM + V4BN) * GLDS;           // 13824 floats
constexpr int GM4_SMEM_BYTES = 3 * STG4 * 4;       // 165888 B

__device__ __forceinline__ void cp_stage4(
    float* st, const float* __restrict__ A, int lda,
    const float* __restrict__ W, int K,
    int bm, int bn, int kk, int tid)
{
#pragma unroll
    for (int i = 0; i < 6; i++) {
        int idx = tid + i * 512;
        int r   = idx >> 3;
        int c4  = (idx & 7) * 4;
        int gk  = kk + c4;
        float* d = st + r * GLDS + c4;
        const float* s = (r < BM) ? (A + (size_t)(bm + r) * lda + gk)
                                  : (W + (size_t)(bn + r - BM) * K + gk);
        if (gk + 4 <= K) {
            cp16(smem_u32(d), s);
        } else {
            float4 v;
            v.x = (gk + 0 < K) ? s[0] : 0.f;
            v.y = (gk + 1 < K) ? s[1] : 0.f;
            v.z = (gk + 2 < K) ? s[2] : 0.f;
            v.w = (gk + 3 < K) ? s[3] : 0.f;
            *reinterpret_cast<float4*>(d) = v;
        }
    }
    asm volatile("cp.async.commit_group;");
}

__global__ void __launch_bounds__(512, 1)
gemm_tf32_v4(const float* __restrict__ A, int lda,
             const float* __restrict__ W,
             const float* __restrict__ bias,
             float* __restrict__ C, int ldc,
             int M, int N, int K, int act, int permute_bt)
{
    extern __shared__ float sm[];
    float* Cs = sm;   // epilogue alias: 128 x 260 floats = 133120 B < 165888

    const int bm  = blockIdx.y * BM;
    const int bn  = blockIdx.x * V4BN;
    const int tid = threadIdx.x;
    const int w   = tid >> 5;
    const int wm  = w & 3;     // 4 warps along M (32 rows each)
    const int wn  = w >> 2;    // 4 warps along N (64 cols each)

    wmma::fragment<wmma::accumulator, 16, 16, 8, float> c[2][4];
#pragma unroll
    for (int i = 0; i < 2; i++)
#pragma unroll
        for (int j = 0; j < 4; j++)
            wmma::fill_fragment(c[i][j], 0.0f);

    const int niter = (K + BK - 1) / BK;

    cp_stage4(sm, A, lda, W, K, bm, bn, 0, tid);
    if (niter > 1) cp_stage4(sm + STG4, A, lda, W, K, bm, bn, BK, tid);

    for (int it = 0; it < niter; it++) {
        if (it + 1 < niter) asm volatile("cp.async.wait_group 1;");
        else                asm volatile("cp.async.wait_group 0;");
        __syncthreads();
        if (it + 2 < niter)
            cp_stage4(sm + ((it + 2) % 3) * STG4, A, lda, W, K, bm, bn,
                      (it + 2) * BK, tid);

        const float* As = sm + (it % 3) * STG4;
        const float* Bs = As + BM * GLDS;
#pragma unroll
        for (int ks = 0; ks < 4; ks++) {
            wmma::fragment<wmma::matrix_a, 16, 16, 8, wmma::precision::tf32, wmma::row_major> af[2];
            wmma::fragment<wmma::matrix_b, 16, 16, 8, wmma::precision::tf32, wmma::col_major> bf[4];
#pragma unroll
            for (int i = 0; i < 2; i++) {
                wmma::load_matrix_sync(af[i], As + (wm * 32 + i * 16) * GLDS + ks * 8, GLDS);
#pragma unroll
                for (int e = 0; e < af[i].num_elements; e++)
                    af[i].x[e] = wmma::__float_to_tf32(af[i].x[e]);
            }
#pragma unroll
            for (int j = 0; j < 4; j++)
                wmma::load_matrix_sync(bf[j], Bs + (wn * 64 + j * 16) * GLDS + ks * 8, GLDS);
#pragma unroll
            for (int i = 0; i < 2; i++)
#pragma unroll
                for (int j = 0; j < 4; j++)
                    wmma::mma_sync(c[i][j], af[i], bf[j], c[i][j]);
        }
    }

    __syncthreads();
#pragma unroll
    for (int i = 0; i < 2; i++)
#pragma unroll
        for (int j = 0; j < 4; j++)
            wmma::store_matrix_sync(Cs + (wm * 32 + i * 16) * (V4BN + 4) + wn * 64 + j * 16,
                                    c[i][j], V4BN + 4, wmma::mem_row_major);
    __syncthreads();

#pragma unroll
    for (int i = 0; i < 16; i++) {
        int idx4 = tid + i * 512;          // 128 x 64 float4s
        int r    = idx4 >> 6;
        int c4   = (idx4 & 63) * 4;
        float4 v = *reinterpret_cast<const float4*>(Cs + r * (V4BN + 4) + c4);
        if (bias) {
            float4 bv = *reinterpret_cast<const float4*>(bias + bn + c4);
            v.x += bv.x; v.y += bv.y; v.z += bv.z; v.w += bv.w;
        }
        if (act == 1) {
            v.x = fmaxf(v.x, 0.f); v.y = fmaxf(v.y, 0.f);
            v.z = fmaxf(v.z, 0.f); v.w = fmaxf(v.w, 0.f);
        }
        int gr   = bm + r;
        int orow = permute_bt ? (((gr & 255) << 8) | (gr >> 8)) : gr;
        *reinterpret_cast<float4*>(C + (size_t)orow * ldc + bn + c4) = v;
    }
}

__global__ void logits_reduce(const float* __restrict__ lpart,
                              const float* __restrict__ b2,
                              float* __restrict__ logits)
{
    int i = blockIdx.x * blockDim.x + threadIdx.x;
    if (i >= BT) return;
    logits[i] = lpart[i] + lpart[BT + i] + lpart[2 * BT + i] +
                lpart[3 * BT + i] + b2[0];
}

// ----------------------------------------------------------------------------
// Whh pre-swizzle (unchanged)
// ----------------------------------------------------------------------------
__global__ void swizzle_whh(const float* __restrict__ whh, float* __restrict__ wsw)
{
    int nt = blockIdx.x;
    int n0 = nt * 16;
    for (int i = threadIdx.x; i < 128 * 6 * 32; i += blockDim.x) {
        int lane  = i & 31;
        int pos   = i >> 5;
        int kstep = pos / 6;
        int g2    = pos % 6;
        int g  = g2 >> 1;
        int nj = g2 & 1;
        int q = lane >> 2, t = lane & 3;
        const float* src = whh + (size_t)(g * H + n0 + nj * 8 + q) * H + kstep * 8 + t;
        float2 v;
        v.x = __uint_as_float(f2tf32(src[0]));
        v.y = __uint_as_float(f2tf32(src[4]));
        *reinterpret_cast<float2*>(wsw + (size_t)nt * WSW_TILE + (size_t)pos * 64 + lane * 2) = v;
    }
}

// ----------------------------------------------------------------------------
// Fused single GRU step v7 (UNCHANGED from round 12)
// ----------------------------------------------------------------------------
constexpr int RC_LDA     = 20;
constexpr int RC_GFLOATS = 3 * 128 * RC_LDA;
constexpr int RC_SMEM_BYTES = RC_GFLOATS * 4;

__global__ void __launch_bounds__(512, 1)
gru_step(const float* __restrict__ wsw, const float* __restrict__ bhh,
         const float* __restrict__ gi, size_t gi_bstride,
         const float* __restrict__ hF_read, float* __restrict__ hF_write,
         float* __restrict__ eout_t, size_t eout_bstride,
         float* __restrict__ hrow_write)
{
    extern __shared__ float Gsm[];

    const int tid  = threadIdx.x;
    const int lane = tid & 31;
    const int w    = tid >> 5;
    const int grp  = w >> 2;
    const int wm   = w & 3;
    const int nt   = blockIdx.x & 63;
    const int bt   = blockIdx.x >> 6;
    const int b0   = bt * 128;
    const int n0   = nt * 16;

    const float2* wg  = reinterpret_cast<const float2*>(wsw + (size_t)nt * WSW_TILE);
    const float4* hF4 = reinterpret_cast<const float4*>(hF_read);
    const int k8base  = grp * 32;
    const int mbb     = bt * 8 + wm * 2;

    float acc[2][3][2][4];
#pragma unroll
    for (int mh = 0; mh < 2; mh++)
#pragma unroll
        for (int g = 0; g < 3; g++)
#pragma unroll
            for (int nj = 0; nj < 2; nj++)
#pragma unroll
                for (int e = 0; e < 4; e++) acc[mh][g][nj][e] = 0.f;

    float4 pf[2];
    float2 wv[6];
#pragma unroll
    for (int mh = 0; mh < 2; mh++)
        pf[mh] = hF4[((size_t)k8base * 16 + mbb + mh) * 32 + lane];
#pragma unroll
    for (int j = 0; j < 6; j++)
        wv[j] = wg[((size_t)(k8base * 6) + j) * 32 + lane];

    for (int c = 0; c < 32; c++) {
        uint32_t A[2][4];
#pragma unroll
        for (int mh = 0; mh < 2; mh++) {
            A[mh][0] = f2tf32(pf[mh].x);
            A[mh][1] = f2tf32(pf[mh].y);
            A[mh][2] = f2tf32(pf[mh].z);
            A[mh][3] = f2tf32(pf[mh].w);
        }
        uint32_t bw0[6], bw1[6];
#pragma unroll
        for (int j = 0; j < 6; j++) {
            bw0[j] = __float_as_uint(wv[j].x);
            bw1[j] = __float_as_uint(wv[j].y);
        }

        if (c < 31) {
#pragma unroll
            for (int mh = 0; mh < 2; mh++)
                pf[mh] = hF4[((size_t)(k8base + c + 1) * 16 + mbb + mh) * 32 + lane];
#pragma unroll
            for (int j = 0; j < 6; j++)
                wv[j] = wg[((size_t)((k8base + c + 1) * 6) + j) * 32 + lane];
        }

#pragma unroll
        for (int g = 0; g < 3; g++) {
#pragma unroll
            for (int nj = 0; nj < 2; nj++) {
                int j = g * 2 + nj;
                mma_tf32(acc[0][g][nj], A[0], bw0[j], bw1[j]);
                mma_tf32(acc[1][g][nj], A[1], bw0[j], bw1[j]);
            }
        }
    }

    const int q = lane >> 2;
    const int t = lane & 3;
    const int ccol = 2 * t;
#pragma unroll
    for (int pass = 3; pass >= 0; pass--) {
        if (grp == pass) {
#pragma unroll
            for (int mh = 0; mh < 2; mh++)
#pragma unroll
                for (int g = 0; g < 3; g++)
#pragma unroll
                    for (int nj = 0; nj < 2; nj++) {
                        int row = wm * 32 + mh * 16 + q;
                        float* b0p = Gsm + (g * 128 + row) * RC_LDA + nj * 8 + ccol;
                        float* b1p = Gsm + (g * 128 + row + 8) * RC_LDA + nj * 8 + ccol;
                        if (pass == 3) {
                            b0p[0] = acc[mh][g][nj][0];
                            b0p[1] = acc[mh][g][nj][1];
                            b1p[0] = acc[mh][g][nj][2];
                            b1p[1] = acc[mh][g][nj][3];
                        } else {
                            b0p[0] += acc[mh][g][nj][0];
                            b0p[1] += acc[mh][g][nj][1];
                            b1p[0] += acc[mh][g][nj][2];
                            b1p[1] += acc[mh][g][nj][3];
                        }
                    }
        }
        __syncthreads();
    }

    {
        const int k8l  = tid >> 8;
        const int mbl  = (tid >> 5) & 7;
        const int ln   = tid & 31;
        const int bq   = ln >> 2;
        const int nq   = ln & 3;
        const size_t fidx = ((size_t)(nt * 2 + k8l) * 16 + (bt * 8 + mbl)) * 32 + ln;

        float4 hv4 = hF4[fidx];
        float outv[4];
#pragma unroll
        for (int kh = 0; kh < 2; kh++) {
#pragma unroll
            for (int rh = 0; rh < 2; rh++) {
                int reg = rh + 2 * kh;
                int bl  = mbl * 16 + bq + 8 * rh;
                int nl  = k8l * 8 + nq + 4 * kh;
                int b   = b0 + bl;
                int nc  = n0 + nl;
                float hr = Gsm[(0 * 128 + bl) * RC_LDA + nl] + bhh[nc];
                float hz = Gsm[(1 * 128 + bl) * RC_LDA + nl] + bhh[H + nc];
                float hn = Gsm[(2 * 128 + bl) * RC_LDA + nl] + bhh[2 * H + nc];
                const float* gib = gi + (size_t)b * gi_bstride;
                float ir = gib[nc], iz = gib[H + nc], in_ = gib[2 * H + nc];
                float r  = sigf(ir + hr);
                float z  = sigf(iz + hz);
                float nn = tanhf(in_ + r * hn);
                float hv = (&hv4.x)[reg];
                float hnew = (1.f - z) * nn + z * hv;
                outv[reg] = hnew;
                if (eout_t) eout_t[(size_t)b * eout_bstride + nc] = hnew;
                if (hrow_write) hrow_write[(size_t)b * H + nc] = hnew;
            }
        }
        float4 o4 = make_float4(outv[0], outv[1], outv[2], outv[3]);
        reinterpret_cast<float4*>(hF_write)[fidx] = o4;
    }
}

// ----------------------------------------------------------------------------
// Small kernels
// ----------------------------------------------------------------------------
__global__ void softmax_kernel(const float* __restrict__ logits,
                               float* __restrict__ wts)
{
    __shared__ float sdata[T];
    int b = blockIdx.x, t = threadIdx.x;
    float v = logits[t * B + b];
    sdata[t] = v;
    __syncthreads();
    for (int s = T / 2; s > 0; s >>= 1) {
        if (t < s) sdata[t] = fmaxf(sdata[t], sdata[t + s]);
        __syncthreads();
    }
    float mx = sdata[0];
    __syncthreads();
    float e = expf(v - mx);
    sdata[t] = e;
    __syncthreads();
    for (int s = T / 2; s > 0; s >>= 1) {
        if (t < s) sdata[t] += sdata[t + s];
        __syncthreads();
    }
    wts[t * B + b] = e / sdata[0];
}

__global__ void pool_kernel(const float* __restrict__ eout,
                            const float* __restrict__ wts,
                            float* __restrict__ hsF,
                            float* __restrict__ rep_out)
{
    __shared__ float w[T];
    int b = blockIdx.x, tid = threadIdx.x;
    w[tid] = wts[tid * B + b];
    __syncthreads();
    for (int h0 = tid; h0 < H; h0 += blockDim.x) {
        const float* base = eout + (size_t)b * H + h0;
        float acc = 0.f;
#pragma unroll 4
        for (int t = 0; t < T; t++) acc += w[t] * base[(size_t)t * B * H];
        hsF[hf_idx(b, h0)] = acc;
        if (rep_out) rep_out[b * H + h0] = acc;
    }
}

__global__ void gather_last(const float* __restrict__ x, float* __restrict__ p0)
{
    int idx = blockIdx.x * blockDim.x + threadIdx.x;
    if (idx >= B * D) return;
    int b = idx / D, dd = idx % D;
    p0[idx] = x[((size_t)b * T + (T - 1)) * D + dd];
}

// ----------------------------------------------------------------------------
// Host driver
// ----------------------------------------------------------------------------
static inline void launch_gemm(const float* A, int lda, const float* W,
                               const float* bias, float* C, int ldc,
                               int M, int N, int K, int act, int permute_bt = 0,
                               int nstore = (1 << 30),
                               const float* lw = nullptr, float* lpart = nullptr)
{
    dim3 grid(N / BN, M / BM);
    gemm_tf32_v3<<<grid, 256, GM_SMEM_BYTES>>>(A, lda, W, bias, C, ldc, M, N, K,
                                               act, permute_bt, nstore, lw, lpart);
}

static inline void launch_gemm4(const float* A, int lda, const float* W,
                                const float* bias, float* C, int ldc,
                                int M, int N, int K, int act, int permute_bt = 0)
{
    dim3 grid(N / V4BN, M / BM);
    gemm_tf32_v4<<<grid, 512, GM4_SMEM_BYTES>>>(A, lda, W, bias, C, ldc, M, N, K,
                                                act, permute_bt);
}

extern "C" void kernel_launch(void* const* d_in, const int* in_sizes, int n_in,
                              void* d_out, int out_size)
{
    const float* x       = (const float*)d_in[0];
    const float* p2l_w1  = (const float*)d_in[2];
    const float* p2l_b1  = (const float*)d_in[3];
    const float* p2l_w2  = (const float*)d_in[4];
    const float* p2l_b2  = (const float*)d_in[5];
    const float* enc_wih = (const float*)d_in[6];
    const float* enc_whh = (const float*)d_in[7];
    const float* enc_bih = (const float*)d_in[8];
    const float* enc_bhh = (const float*)d_in[9];
    const float* dec_wih = (const float*)d_in[10];
    const float* dec_whh = (const float*)d_in[11];
    const float* dec_bih = (const float*)d_in[12];
    const float* dec_bhh = (const float*)d_in[13];
    const float* l2p_w1  = (const float*)d_in[14];
    const float* l2p_b1  = (const float*)d_in[15];
    const float* l2p_w2  = (const float*)d_in[16];
    const float* l2p_b2  = (const float*)d_in[17];
    const float* l2s_w1  = (const float*)d_in[18];
    const float* l2s_b1  = (const float*)d_in[19];
    const float* l2s_w2  = (const float*)d_in[20];
    const float* l2s_b2  = (const float*)d_in[21];

    float* out = (float*)d_out;
    const int PREDS = B * P * D;
    float* rep_out = (out_size >= PREDS + B * H) ? (out + PREDS) : nullptr;

    float *p_buf1, *p_latent, *p_xp, *p_eout, *p_hb0, *p_hb1, *p_logits,
          *p_lpart, *p_wts, *p_hs, *p_hs2, *p_hrow, *p_p0, *p_d1, *p_dinp,
          *p_gi, *p_l1, *p_wsw_enc, *p_wsw_dec, *p_wtf, *p_wl2p2, *p_bl2p2;
    void* tmp;
#define SYM(dst, sym) cudaGetSymbolAddress(&tmp, sym); dst = (decltype(dst))tmp;
    SYM(p_buf1, g_buf1)   SYM(p_latent, g_latent) SYM(p_xp, g_xp)
    SYM(p_eout, g_eout)   SYM(p_hb0, g_hb0)       SYM(p_hb1, g_hb1)
    SYM(p_logits, g_logits) SYM(p_lpart, g_lpart) SYM(p_wts, g_wts)
    SYM(p_hs, g_hs)       SYM(p_hs2, g_hs2)       SYM(p_hrow, g_hrow)
    SYM(p_p0, g_p0)       SYM(p_d1, g_d1)         SYM(p_dinp, g_dinp)
    SYM(p_gi, g_gi)       SYM(p_l1, g_l1)         SYM(p_wsw_enc, g_wsw_enc)
    SYM(p_wsw_dec, g_wsw_dec) SYM(p_wtf, g_wtf)   SYM(p_wl2p2, g_wl2p2)
    SYM(p_bl2p2, g_bl2p2)
#undef SYM

    float* w_p2l1   = p_wtf + WT_P2L1;
    float* w_p2l2   = p_wtf + WT_P2L2;
    float* w_encwih = p_wtf + WT_ENCWIH;
    float* w_l2s1   = p_wtf + WT_L2S1;
    float* w_decwih = p_wtf + WT_DECWIH;
    float* w_l2p1   = p_wtf + WT_L2P1;

    cudaFuncSetAttribute(gru_step, cudaFuncAttributeMaxDynamicSharedMemorySize,
                         RC_SMEM_BYTES);
    cudaFuncSetAttribute(gemm_tf32_v3, cudaFuncAttributeMaxDynamicSharedMemorySize,
                         GM_SMEM_BYTES);
    cudaFuncSetAttribute(gemm_tf32_v4, cudaFuncAttributeMaxDynamicSharedMemorySize,
                         GM4_SMEM_BYTES);

    // ---- one-time weight preprocessing (4 launches) ----
    swizzle_whh<<<64, 256>>>(enc_whh, p_wsw_enc);
    swizzle_whh<<<64, 256>>>(dec_whh, p_wsw_dec);
    cvt_all<<<(CN5 + 255) / 256, 256>>>(p2l_w1, p2l_w2, enc_wih, l2s_w1,
                                        dec_wih, l2p_w1, p_wtf);
    pad_l2p2<<<(128 * 512 + 255) / 256, 256>>>(l2p_w2, l2p_b2, p_wl2p2, p_bl2p2);

    // ---- par2lat(x) ----
    launch_gemm(x, D, w_p2l1, p2l_b1, p_buf1, HID, BT, HID, D, 1);
    launch_gemm4(p_buf1, HID, w_p2l2, p2l_b2, p_latent, H, BT, H, HID, 1);

    // ---- xp = latent @ enc_wih^T + enc_bih, t-major [T, B, 3H] ----
    launch_gemm4(p_latent, H, w_encwih, enc_bih, p_xp, H3, BT, H3, H, 0, 1);

    // ---- encoder recurrence ----
    cudaMemsetAsync(p_hb0, 0, (size_t)B * H * sizeof(float));
    {
        float* hr = p_hb0;
        float* hw = p_hb1;
        for (int t = 0; t < T; t++) {
            gru_step<<<128, 512, RC_SMEM_BYTES>>>(
                p_wsw_enc, enc_bhh,
                p_xp + (size_t)t * B * H3, (size_t)H3,
                hr, hw,
                p_eout + (size_t)t * B * H, (size_t)H,
                nullptr);
            float* t2 = hr; hr = hw; hw = t2;
        }
    }

    // ---- attention pooling: fused s1-GEMM + logits dot ----
    launch_gemm(p_eout, H, w_l2s1, l2s_b1, nullptr, HID, BT, HID, H, 1, 0,
                (1 << 30), l2s_w2, p_lpart);
    logits_reduce<<<BT / 256, 256>>>(p_lpart, l2s_b2, p_logits);
    softmax_kernel<<<B, T>>>(p_logits, p_wts);
    pool_kernel<<<B, 256>>>(p_eout, p_wts, p_hs, rep_out);

    // ---- autoregressive decode ----
    gather_last<<<(B * D + 255) / 256, 256>>>(x, p_p0);
    float* hF_read  = p_hs;
    float* hF_write = p_hs2;
    for (int s = 0; s < P; s++) {
        const float* pin = (s == 0) ? p_p0 : (out + (size_t)(s - 1) * D);
        int plda = (s == 0) ? D : (P * D);
        launch_gemm(pin, plda, w_p2l1, p2l_b1, p_d1, HID, B, HID, D, 1);
        launch_gemm4(p_d1, HID, w_p2l2, p2l_b2, p_dinp, H, B, H, HID, 1);
        launch_gemm4(p_dinp, H, w_decwih, dec_bih, p_gi, H3, B, H3, H, 0);
        gru_step<<<128, 512, RC_SMEM_BYTES>>>(
            p_wsw_dec, dec_bhh, p_gi, (size_t)H3,
            hF_read, hF_write, nullptr, 0, p_hrow);
        launch_gemm(p_hrow, H, w_l2p1, l2p_b1, p_l1, HID, B, HID, H, 1);
        // pred as masked-N GEMM: M=256, N=128 (store 72), K=512
        launch_gemm(p_l1, HID, p_wl2p2, p_bl2p2, out + (size_t)s * D, P * D,
                    B, 128, HID, 0, 0, D);
        float* t2 = hF_read; hF_read = hF_write; hF_write = t2;
    }
}

// round 14
// speedup vs baseline: 1.0480x; 1.0480x over previous
#include <cuda_runtime.h>
#include <mma.h>
#include <cstdint>

using namespace nvcuda;

constexpr int B   = 256;
constexpr int T   = 256;
constexpr int D   = 72;
constexpr int HID = 512;
constexpr int H   = 1024;
constexpr int H3  = 3 * H;
constexpr int P   = 10;
constexpr int BT  = B * T;

// ----------------------------------------------------------------------------
// Device scratch
// ----------------------------------------------------------------------------
__device__ float g_buf1  [(size_t)BT * HID];
__device__ float g_latent[(size_t)BT * H];
__device__ float g_xp    [(size_t)BT * H3];   // [T, B, 3H]
__device__ float g_eout  [(size_t)BT * H];    // [T, B, H]
__device__ float g_hb0   [B * H];             // hF fragment-order
__device__ float g_hb1   [B * H];
__device__ float g_logits[BT];
__device__ float g_lpart [4 * BT];
__device__ float g_wts   [BT];
__device__ float g_hs    [B * H];
__device__ float g_hs2   [B * H];
__device__ float g_hrow  [B * H];
__device__ float g_p0    [B * D];
__device__ float g_d1    [B * HID];
__device__ float g_dinp  [B * H];
__device__ float g_gi    [B * H3];
__device__ float g_l1    [B * HID];
constexpr int WSW_TILE = 128 * 6 * 64;
__device__ float g_wsw_enc[(size_t)64 * WSW_TILE];
__device__ float g_wsw_dec[(size_t)64 * WSW_TILE];
constexpr size_t WT_P2L1   = 0;
constexpr size_t WT_P2L2   = WT_P2L1 + 512 * 72;
constexpr size_t WT_ENCWIH = WT_P2L2 + 1024 * 512;
constexpr size_t WT_L2S1   = WT_ENCWIH + (size_t)3072 * 1024;
constexpr size_t WT_DECWIH = WT_L2S1 + 512 * 1024;
constexpr size_t WT_L2P1   = WT_DECWIH + (size_t)3072 * 1024;
constexpr size_t WT_TOTAL  = WT_L2P1 + 512 * 1024;
__device__ float g_wtf[WT_TOTAL];
__device__ float g_wl2p2[128 * 512];
__device__ float g_bl2p2[128];

__device__ __forceinline__ size_t hf_idx(int b, int k) {
    return ((((size_t)(k >> 3) * 16 + (b >> 4)) * 32 +
             ((b & 7) * 4 + (k & 3))) << 2) +
           (((b >> 3) & 1) + 2 * ((k >> 2) & 1));
}

__device__ __forceinline__ float sigf(float x) { return 1.f / (1.f + expf(-x)); }

__device__ __forceinline__ uint32_t f2tf32(float x) {
    uint32_t r;
    asm("cvt.rna.tf32.f32 %0, %1;" : "=r"(r) : "f"(x));
    return r;
}

__device__ __forceinline__ void mma_tf32(float d[4], const uint32_t a[4],
                                         uint32_t b0, uint32_t b1) {
    asm volatile(
        "mma.sync.aligned.m16n8k8.row.col.f32.tf32.tf32.f32 "
        "{%0,%1,%2,%3}, {%4,%5,%6,%7}, {%8,%9}, {%0,%1,%2,%3};"
        : "+f"(d[0]), "+f"(d[1]), "+f"(d[2]), "+f"(d[3])
        : "r"(a[0]), "r"(a[1]), "r"(a[2]), "r"(a[3]), "r"(b0), "r"(b1));
}

__device__ __forceinline__ uint32_t smem_u32(const void* p) {
    return (uint32_t)__cvta_generic_to_shared(p);
}
__device__ __forceinline__ void cp16(uint32_t dst, const void* src) {
    asm volatile("cp.async.ca.shared.global [%0], [%1], 16;" :: "r"(dst), "l"(src));
}

// ----------------------------------------------------------------------------
// Merged tf32 weight rounding (6 segments -> g_wtf)
// ----------------------------------------------------------------------------
constexpr int CN0 = 512 * 72 / 4;
constexpr int CN1 = CN0 + 1024 * 512 / 4;
constexpr int CN2 = CN1 + 3072 * 1024 / 4;
constexpr int CN3 = CN2 + 512 * 1024 / 4;
constexpr int CN4 = CN3 + 3072 * 1024 / 4;
constexpr int CN5 = CN4 + 512 * 1024 / 4;

__global__ void cvt_all(const float* __restrict__ s0, const float* __restrict__ s1,
                        const float* __restrict__ s2, const float* __restrict__ s3,
                        const float* __restrict__ s4, const float* __restrict__ s5,
                        float* __restrict__ dst)
{
    int i = blockIdx.x * blockDim.x + threadIdx.x;
    if (i >= CN5) return;
    const float* src; int off;
    if      (i < CN0) { src = s0; off = i; }
    else if (i < CN1) { src = s1; off = i - CN0; }
    else if (i < CN2) { src = s2; off = i - CN1; }
    else if (i < CN3) { src = s3; off = i - CN2; }
    else if (i < CN4) { src = s4; off = i - CN3; }
    else              { src = s5; off = i - CN4; }
    float4 v = reinterpret_cast<const float4*>(src)[off];
    v.x = __uint_as_float(f2tf32(v.x));
    v.y = __uint_as_float(f2tf32(v.y));
    v.z = __uint_as_float(f2tf32(v.z));
    v.w = __uint_as_float(f2tf32(v.w));
    reinterpret_cast<float4*>(dst)[i] = v;
}

__global__ void pad_l2p2(const float* __restrict__ w2, const float* __restrict__ b2,
                         float* __restrict__ wp, float* __restrict__ bp)
{
    int i = blockIdx.x * blockDim.x + threadIdx.x;
    if (i < 128 * 512) {
        int r = i / 512;
        wp[i] = (r < D) ? __uint_as_float(f2tf32(w2[(size_t)r * 512 + (i % 512)])) : 0.f;
    }
    if (i < 128) bp[i] = (i < D) ? b2[i] : 0.f;
}

// ----------------------------------------------------------------------------
// GEMM v3 (128x128, 256 thr, 2 CTAs/SM, 3-stage cp.async) — the proven one.
// nstore mask for padded-N stores; fused-logits mode via lw/lpart.
// ----------------------------------------------------------------------------
#define BM 128
#define BN 128
#define BK 32
constexpr int GLDS = BK + 4;
constexpr int STG  = (BM + BN) * GLDS;
constexpr int GM_SMEM_BYTES = 3 * STG * 4;

__device__ __forceinline__ void cp_stage(
    float* st, const float* __restrict__ A, int lda,
    const float* __restrict__ W, int K,
    int bm, int bn, int kk, int tid)
{
#pragma unroll
    for (int i = 0; i < 4; i++) {
        int idx = tid + i * 256;
        int r   = idx >> 3;
        int c4  = (idx & 7) * 4;
        int gk  = kk + c4;
        float* da = st + r * GLDS + c4;
        float* db = st + (BM + r) * GLDS + c4;
        const float* sa = A + (size_t)(bm + r) * lda + gk;
        const float* sb = W + (size_t)(bn + r) * K + gk;
        if (gk + 4 <= K) {
            cp16(smem_u32(da), sa);
            cp16(smem_u32(db), sb);
        } else {
            float4 va, vb;
            va.x = (gk + 0 < K) ? sa[0] : 0.f;  vb.x = (gk + 0 < K) ? sb[0] : 0.f;
            va.y = (gk + 1 < K) ? sa[1] : 0.f;  vb.y = (gk + 1 < K) ? sb[1] : 0.f;
            va.z = (gk + 2 < K) ? sa[2] : 0.f;  vb.z = (gk + 2 < K) ? sb[2] : 0.f;
            va.w = (gk + 3 < K) ? sa[3] : 0.f;  vb.w = (gk + 3 < K) ? sb[3] : 0.f;
            *reinterpret_cast<float4*>(da) = va;
            *reinterpret_cast<float4*>(db) = vb;
        }
    }
    asm volatile("cp.async.commit_group;");
}

__global__ void __launch_bounds__(256, 2)
gemm_tf32_v3(const float* __restrict__ A, int lda,
             const float* __restrict__ W,
             const float* __restrict__ bias,
             float* __restrict__ C, int ldc,
             int M, int N, int K, int act, int permute_bt, int nstore,
             const float* __restrict__ lw, float* __restrict__ lpart)
{
    extern __shared__ float sm[];
    float* Cs = sm;

    const int bm  = blockIdx.y * BM;
    const int bn  = blockIdx.x * BN;
    const int tid = threadIdx.x;
    const int w   = tid >> 5;
    const int wm  = w & 3;
    const int wn  = w >> 2;

    wmma::fragment<wmma::accumulator, 16, 16, 8, float> c[2][4];
#pragma unroll
    for (int i = 0; i < 2; i++)
#pragma unroll
        for (int j = 0; j < 4; j++)
            wmma::fill_fragment(c[i][j], 0.0f);

    const int niter = (K + BK - 1) / BK;

    cp_stage(sm, A, lda, W, K, bm, bn, 0, tid);
    if (niter > 1) cp_stage(sm + STG, A, lda, W, K, bm, bn, BK, tid);

    for (int it = 0; it < niter; it++) {
        if (it + 1 < niter) asm volatile("cp.async.wait_group 1;");
        else                asm volatile("cp.async.wait_group 0;");
        __syncthreads();
        if (it + 2 < niter)
            cp_stage(sm + ((it + 2) % 3) * STG, A, lda, W, K, bm, bn,
                     (it + 2) * BK, tid);

        const float* As = sm + (it % 3) * STG;
        const float* Bs = As + BM * GLDS;
#pragma unroll
        for (int ks = 0; ks < 4; ks++) {
            wmma::fragment<wmma::matrix_a, 16, 16, 8, wmma::precision::tf32, wmma::row_major> af[2];
            wmma::fragment<wmma::matrix_b, 16, 16, 8, wmma::precision::tf32, wmma::col_major> bf[4];
#pragma unroll
            for (int i = 0; i < 2; i++) {
                wmma::load_matrix_sync(af[i], As + (wm * 32 + i * 16) * GLDS + ks * 8, GLDS);
#pragma unroll
                for (int e = 0; e < af[i].num_elements; e++)
                    af[i].x[e] = wmma::__float_to_tf32(af[i].x[e]);
            }
#pragma unroll
            for (int j = 0; j < 4; j++)
                wmma::load_matrix_sync(bf[j], Bs + (wn * 64 + j * 16) * GLDS + ks * 8, GLDS);
#pragma unroll
            for (int i = 0; i < 2; i++)
#pragma unroll
                for (int j = 0; j < 4; j++)
                    wmma::mma_sync(c[i][j], af[i], bf[j], c[i][j]);
        }
    }

    __syncthreads();
#pragma unroll
    for (int i = 0; i < 2; i++)
#pragma unroll
        for (int j = 0; j < 4; j++)
            wmma::store_matrix_sync(Cs + (wm * 32 + i * 16) * (BN + 4) + wn * 64 + j * 16,
                                    c[i][j], BN + 4, wmma::mem_row_major);
    __syncthreads();

#pragma unroll
    for (int i = 0; i < 16; i++) {
        int idx4 = tid + i * 256;
        int r    = idx4 >> 5;
        int c4   = (idx4 & 31) * 4;
        float4 v = *reinterpret_cast<const float4*>(Cs + r * (BN + 4) + c4);
        if (bias) {
            float4 bv = *reinterpret_cast<const float4*>(bias + bn + c4);
            v.x += bv.x; v.y += bv.y; v.z += bv.z; v.w += bv.w;
        }
        if (act == 1) {
            v.x = fmaxf(v.x, 0.f); v.y = fmaxf(v.y, 0.f);
            v.z = fmaxf(v.z, 0.f); v.w = fmaxf(v.w, 0.f);
        }
        int gr   = bm + r;
        int orow = permute_bt ? (((gr & 255) << 8) | (gr >> 8)) : gr;
        if (!lpart) {
            if (bn + c4 < nstore)
                *reinterpret_cast<float4*>(C + (size_t)orow * ldc + bn + c4) = v;
        } else {
            float4 wv4 = *reinterpret_cast<const float4*>(lw + bn + c4);
            float d = v.x * wv4.x + v.y * wv4.y + v.z * wv4.z + v.w * wv4.w;
#pragma unroll
            for (int o = 16; o > 0; o >>= 1)
                d += __shfl_xor_sync(0xffffffffu, d, o);
            if ((tid & 31) == 0)
                lpart[(size_t)(bn >> 7) * M + orow] = d;
        }
    }
}

__global__ void logits_reduce(const float* __restrict__ lpart,
                              const float* __restrict__ b2,
                              float* __restrict__ logits)
{
    int i = blockIdx.x * blockDim.x + threadIdx.x;
    if (i >= BT) return;
    logits[i] = lpart[i] + lpart[BT + i] + lpart[2 * BT + i] +
                lpart[3 * BT + i] + b2[0];
}

// ----------------------------------------------------------------------------
// Whh pre-swizzle (unchanged)
// ----------------------------------------------------------------------------
__global__ void swizzle_whh(const float* __restrict__ whh, float* __restrict__ wsw)
{
    int nt = blockIdx.x;
    int n0 = nt * 16;
    for (int i = threadIdx.x; i < 128 * 6 * 32; i += blockDim.x) {
        int lane  = i & 31;
        int pos   = i >> 5;
        int kstep = pos / 6;
        int g2    = pos % 6;
        int g  = g2 >> 1;
        int nj = g2 & 1;
        int q = lane >> 2, t = lane & 3;
        const float* src = whh + (size_t)(g * H + n0 + nj * 8 + q) * H + kstep * 8 + t;
        float2 v;
        v.x = __uint_as_float(f2tf32(src[0]));
        v.y = __uint_as_float(f2tf32(src[4]));
        *reinterpret_cast<float2*>(wsw + (size_t)nt * WSW_TILE + (size_t)pos * 64 + lane * 2) = v;
    }
}

// ----------------------------------------------------------------------------
// Fused single GRU step v7 (proven)
// ----------------------------------------------------------------------------
constexpr int RC_LDA     = 20;
constexpr int RC_GFLOATS = 3 * 128 * RC_LDA;
constexpr int RC_SMEM_BYTES = RC_GFLOATS * 4;

__global__ void __launch_bounds__(512, 1)
gru_step(const float* __restrict__ wsw, const float* __restrict__ bhh,
         const float* __restrict__ gi, size_t gi_bstride,
         const float* __restrict__ hF_read, float* __restrict__ hF_write,
         float* __restrict__ eout_t, size_t eout_bstride,
         float* __restrict__ hrow_write)
{
    extern __shared__ float Gsm[];

    const int tid  = threadIdx.x;
    const int lane = tid & 31;
    const int w    = tid >> 5;
    const int grp  = w >> 2;
    const int wm   = w & 3;
    const int nt   = blockIdx.x & 63;
    const int bt   = blockIdx.x >> 6;
    const int b0   = bt * 128;
    const int n0   = nt * 16;

    const float2* wg  = reinterpret_cast<const float2*>(wsw + (size_t)nt * WSW_TILE);
    const float4* hF4 = reinterpret_cast<const float4*>(hF_read);
    const int k8base  = grp * 32;
    const int mbb     = bt * 8 + wm * 2;

    float acc[2][3][2][4];
#pragma unroll
    for (int mh = 0; mh < 2; mh++)
#pragma unroll
        for (int g = 0; g < 3; g++)
#pragma unroll
            for (int nj = 0; nj < 2; nj++)
#pragma unroll
                for (int e = 0; e < 4; e++) acc[mh][g][nj][e] = 0.f;

    float4 pf[2];
    float2 wv[6];
#pragma unroll
    for (int mh = 0; mh < 2; mh++)
        pf[mh] = hF4[((size_t)k8base * 16 + mbb + mh) * 32 + lane];
#pragma unroll
    for (int j = 0; j < 6; j++)
        wv[j] = wg[((size_t)(k8base * 6) + j) * 32 + lane];

    for (int c = 0; c < 32; c++) {
        uint32_t A[2][4];
#pragma unroll
        for (int mh = 0; mh < 2; mh++) {
            A[mh][0] = f2tf32(pf[mh].x);
            A[mh][1] = f2tf32(pf[mh].y);
            A[mh][2] = f2tf32(pf[mh].z);
            A[mh][3] = f2tf32(pf[mh].w);
        }
        uint32_t bw0[6], bw1[6];
#pragma unroll
        for (int j = 0; j < 6; j++) {
            bw0[j] = __float_as_uint(wv[j].x);
            bw1[j] = __float_as_uint(wv[j].y);
        }

        if (c < 31) {
#pragma unroll
            for (int mh = 0; mh < 2; mh++)
                pf[mh] = hF4[((size_t)(k8base + c + 1) * 16 + mbb + mh) * 32 + lane];
#pragma unroll
            for (int j = 0; j < 6; j++)
                wv[j] = wg[((size_t)((k8base + c + 1) * 6) + j) * 32 + lane];
        }

#pragma unroll
        for (int g = 0; g < 3; g++) {
#pragma unroll
            for (int nj = 0; nj < 2; nj++) {
                int j = g * 2 + nj;
                mma_tf32(acc[0][g][nj], A[0], bw0[j], bw1[j]);
                mma_tf32(acc[1][g][nj], A[1], bw0[j], bw1[j]);
            }
        }
    }

    const int q = lane >> 2;
    const int t = lane & 3;
    const int ccol = 2 * t;
#pragma unroll
    for (int pass = 3; pass >= 0; pass--) {
        if (grp == pass) {
#pragma unroll
            for (int mh = 0; mh < 2; mh++)
#pragma unroll
                for (int g = 0; g < 3; g++)
#pragma unroll
                    for (int nj = 0; nj < 2; nj++) {
                        int row = wm * 32 + mh * 16 + q;
                        float* b0p = Gsm + (g * 128 + row) * RC_LDA + nj * 8 + ccol;
                        float* b1p = Gsm + (g * 128 + row + 8) * RC_LDA + nj * 8 + ccol;
                        if (pass == 3) {
                            b0p[0] = acc[mh][g][nj][0];
                            b0p[1] = acc[mh][g][nj][1];
                            b1p[0] = acc[mh][g][nj][2];
                            b1p[1] = acc[mh][g][nj][3];
                        } else {
                            b0p[0] += acc[mh][g][nj][0];
                            b0p[1] += acc[mh][g][nj][1];
                            b1p[0] += acc[mh][g][nj][2];
                            b1p[1] += acc[mh][g][nj][3];
                        }
                    }
        }
        __syncthreads();
    }

    {
        const int k8l  = tid >> 8;
        const int mbl  = (tid >> 5) & 7;
        const int ln   = tid & 31;
        const int bq   = ln >> 2;
        const int nq   = ln & 3;
        const size_t fidx = ((size_t)(nt * 2 + k8l) * 16 + (bt * 8 + mbl)) * 32 + ln;

        float4 hv4 = hF4[fidx];
        float outv[4];
#pragma unroll
        for (int kh = 0; kh < 2; kh++) {
#pragma unroll
            for (int rh = 0; rh < 2; rh++) {
                int reg = rh + 2 * kh;
                int bl  = mbl * 16 + bq + 8 * rh;
                int nl  = k8l * 8 + nq + 4 * kh;
                int b   = b0 + bl;
                int nc  = n0 + nl;
                float hr = Gsm[(0 * 128 + bl) * RC_LDA + nl] + bhh[nc];
                float hz = Gsm[(1 * 128 + bl) * RC_LDA + nl] + bhh[H + nc];
                float hn = Gsm[(2 * 128 + bl) * RC_LDA + nl] + bhh[2 * H + nc];
                const float* gib = gi + (size_t)b * gi_bstride;
                float ir = gib[nc], iz = gib[H + nc], in_ = gib[2 * H + nc];
                float r  = sigf(ir + hr);
                float z  = sigf(iz + hz);
                float nn = tanhf(in_ + r * hn);
                float hv = (&hv4.x)[reg];
                float hnew = (1.f - z) * nn + z * hv;
                outv[reg] = hnew;
                if (eout_t) eout_t[(size_t)b * eout_bstride + nc] = hnew;
                if (hrow_write) hrow_write[(size_t)b * H + nc] = hnew;
            }
        }
        float4 o4 = make_float4(outv[0], outv[1], outv[2], outv[3]);
        reinterpret_cast<float4*>(hF_write)[fidx] = o4;
    }
}

// ----------------------------------------------------------------------------
// Small kernels
// ----------------------------------------------------------------------------
__global__ void softmax_kernel(const float* __restrict__ logits,
                               float* __restrict__ wts)
{
    __shared__ float sdata[T];
    int b = blockIdx.x, t = threadIdx.x;
    float v = logits[t * B + b];
    sdata[t] = v;
    __syncthreads();
    for (int s = T / 2; s > 0; s >>= 1) {
        if (t < s) sdata[t] = fmaxf(sdata[t], sdata[t + s]);
        __syncthreads();
    }
    float mx = sdata[0];
    __syncthreads();
    float e = expf(v - mx);
    sdata[t] = e;
    __syncthreads();
    for (int s = T / 2; s > 0; s >>= 1) {
        if (t < s) sdata[t] += sdata[t + s];
        __syncthreads();
    }
    wts[t * B + b] = e / sdata[0];
}

__global__ void pool_kernel(const float* __restrict__ eout,
                            const float* __restrict__ wts,
                            float* __restrict__ hsF,
                            float* __restrict__ rep_out)
{
    __shared__ float w[T];
    int b = blockIdx.x, tid = threadIdx.x;
    w[tid] = wts[tid * B + b];
    __syncthreads();
    for (int h0 = tid; h0 < H; h0 += blockDim.x) {
        const float* base = eout + (size_t)b * H + h0;
        float acc = 0.f;
#pragma unroll 4
        for (int t = 0; t < T; t++) acc += w[t] * base[(size_t)t * B * H];
        hsF[hf_idx(b, h0)] = acc;
        if (rep_out) rep_out[b * H + h0] = acc;
    }
}

__global__ void gather_last(const float* __restrict__ x, float* __restrict__ p0)
{
    int idx = blockIdx.x * blockDim.x + threadIdx.x;
    if (idx >= B * D) return;
    int b = idx / D, dd = idx % D;
    p0[idx] = x[((size_t)b * T + (T - 1)) * D + dd];
}

// ----------------------------------------------------------------------------
// Host driver — v3 for EVERY GEMM (v4 reverted)
// ----------------------------------------------------------------------------
static inline void launch_gemm(const float* A, int lda, const float* W,
                               const float* bias, float* C, int ldc,
                               int M, int N, int K, int act, int permute_bt = 0,
                               int nstore = (1 << 30),
                               const float* lw = nullptr, float* lpart = nullptr)
{
    dim3 grid(N / BN, M / BM);
    gemm_tf32_v3<<<grid, 256, GM_SMEM_BYTES>>>(A, lda, W, bias, C, ldc, M, N, K,
                                               act, permute_bt, nstore, lw, lpart);
}

extern "C" void kernel_launch(void* const* d_in, const int* in_sizes, int n_in,
                              void* d_out, int out_size)
{
    const float* x       = (const float*)d_in[0];
    const float* p2l_w1  = (const float*)d_in[2];
    const float* p2l_b1  = (const float*)d_in[3];
    const float* p2l_w2  = (const float*)d_in[4];
    const float* p2l_b2  = (const float*)d_in[5];
    const float* enc_wih = (const float*)d_in[6];
    const float* enc_whh = (const float*)d_in[7];
    const float* enc_bih = (const float*)d_in[8];
    const float* enc_bhh = (const float*)d_in[9];
    const float* dec_wih = (const float*)d_in[10];
    const float* dec_whh = (const float*)d_in[11];
    const float* dec_bih = (const float*)d_in[12];
    const float* dec_bhh = (const float*)d_in[13];
    const float* l2p_w1  = (const float*)d_in[14];
    const float* l2p_b1  = (const float*)d_in[15];
    const float* l2p_w2  = (const float*)d_in[16];
    const float* l2p_b2  = (const float*)d_in[17];
    const float* l2s_w1  = (const float*)d_in[18];
    const float* l2s_b1  = (const float*)d_in[19];
    const float* l2s_w2  = (const float*)d_in[20];
    const float* l2s_b2  = (const float*)d_in[21];

    float* out = (float*)d_out;
    const int PREDS = B * P * D;
    float* rep_out = (out_size >= PREDS + B * H) ? (out + PREDS) : nullptr;

    float *p_buf1, *p_latent, *p_xp, *p_eout, *p_hb0, *p_hb1, *p_logits,
          *p_lpart, *p_wts, *p_hs, *p_hs2, *p_hrow, *p_p0, *p_d1, *p_dinp,
          *p_gi, *p_l1, *p_wsw_enc, *p_wsw_dec, *p_wtf, *p_wl2p2, *p_bl2p2;
    void* tmp;
#define SYM(dst, sym) cudaGetSymbolAddress(&tmp, sym); dst = (decltype(dst))tmp;
    SYM(p_buf1, g_buf1)   SYM(p_latent, g_latent) SYM(p_xp, g_xp)
    SYM(p_eout, g_eout)   SYM(p_hb0, g_hb0)       SYM(p_hb1, g_hb1)
    SYM(p_logits, g_logits) SYM(p_lpart, g_lpart) SYM(p_wts, g_wts)
    SYM(p_hs, g_hs)       SYM(p_hs2, g_hs2)       SYM(p_hrow, g_hrow)
    SYM(p_p0, g_p0)       SYM(p_d1, g_d1)         SYM(p_dinp, g_dinp)
    SYM(p_gi, g_gi)       SYM(p_l1, g_l1)         SYM(p_wsw_enc, g_wsw_enc)
    SYM(p_wsw_dec, g_wsw_dec) SYM(p_wtf, g_wtf)   SYM(p_wl2p2, g_wl2p2)
    SYM(p_bl2p2, g_bl2p2)
#undef SYM

    float* w_p2l1   = p_wtf + WT_P2L1;
    float* w_p2l2   = p_wtf + WT_P2L2;
    float* w_encwih = p_wtf + WT_ENCWIH;
    float* w_l2s1   = p_wtf + WT_L2S1;
    float* w_decwih = p_wtf + WT_DECWIH;
    float* w_l2p1   = p_wtf + WT_L2P1;

    cudaFuncSetAttribute(gru_step, cudaFuncAttributeMaxDynamicSharedMemorySize,
                         RC_SMEM_BYTES);
    cudaFuncSetAttribute(gemm_tf32_v3, cudaFuncAttributeMaxDynamicSharedMemorySize,
                         GM_SMEM_BYTES);

    // ---- one-time weight preprocessing ----
    swizzle_whh<<<64, 256>>>(enc_whh, p_wsw_enc);
    swizzle_whh<<<64, 256>>>(dec_whh, p_wsw_dec);
    cvt_all<<<(CN5 + 255) / 256, 256>>>(p2l_w1, p2l_w2, enc_wih, l2s_w1,
                                        dec_wih, l2p_w1, p_wtf);
    pad_l2p2<<<(128 * 512 + 255) / 256, 256>>>(l2p_w2, l2p_b2, p_wl2p2, p_bl2p2);

    // ---- par2lat(x) ----
    launch_gemm(x, D, w_p2l1, p2l_b1, p_buf1, HID, BT, HID, D, 1);
    launch_gemm(p_buf1, HID, w_p2l2, p2l_b2, p_latent, H, BT, H, HID, 1);

    // ---- xp = latent @ enc_wih^T + enc_bih, t-major [T, B, 3H] ----
    launch_gemm(p_latent, H, w_encwih, enc_bih, p_xp, H3, BT, H3, H, 0, 1);

    // ---- encoder recurrence ----
    cudaMemsetAsync(p_hb0, 0, (size_t)B * H * sizeof(float));
    {
        float* hr = p_hb0;
        float* hw = p_hb1;
        for (int t = 0; t < T; t++) {
            gru_step<<<128, 512, RC_SMEM_BYTES>>>(
                p_wsw_enc, enc_bhh,
                p_xp + (size_t)t * B * H3, (size_t)H3,
                hr, hw,
                p_eout + (size_t)t * B * H, (size_t)H,
                nullptr);
            float* t2 = hr; hr = hw; hw = t2;
        }
    }

    // ---- attention pooling: fused s1-GEMM + logits dot ----
    launch_gemm(p_eout, H, w_l2s1, l2s_b1, nullptr, HID, BT, HID, H, 1, 0,
                (1 << 30), l2s_w2, p_lpart);
    logits_reduce<<<BT / 256, 256>>>(p_lpart, l2s_b2, p_logits);
    softmax_kernel<<<B, T>>>(p_logits, p_wts);
    pool_kernel<<<B, 256>>>(p_eout, p_wts, p_hs, rep_out);

    // ---- autoregressive decode ----
    gather_last<<<(B * D + 255) / 256, 256>>>(x, p_p0);
    float* hF_read  = p_hs;
    float* hF_write = p_hs2;
    for (int s = 0; s < P; s++) {
        const float* pin = (s == 0) ? p_p0 : (out + (size_t)(s - 1) * D);
        int plda = (s == 0) ? D : (P * D);
        launch_gemm(pin, plda, w_p2l1, p2l_b1, p_d1, HID, B, HID, D, 1);
        launch_gemm(p_d1, HID, w_p2l2, p2l_b2, p_dinp, H, B, H, HID, 1);
        launch_gemm(p_dinp, H, w_decwih, dec_bih, p_gi, H3, B, H3, H, 0);
        gru_step<<<128, 512, RC_SMEM_BYTES>>>(
            p_wsw_dec, dec_bhh, p_gi, (size_t)H3,
            hF_read, hF_write, nullptr, 0, p_hrow);
        launch_gemm(p_hrow, H, w_l2p1, l2p_b1, p_l1, HID, B, HID, H, 1);
        // pred as masked-N GEMM: M=256, N=128 (store 72), K=512
        launch_gemm(p_l1, HID, p_wl2p2, p_bl2p2, out + (size_t)s * D, P * D,
                    B, 128, HID, 0, 0, D);
        float* t2 = hF_read; hF_read = hF_write; hF_write = t2;
    }
}

// round 15
// speedup vs baseline: 1.0559x; 1.0076x over previous
#include <cuda_runtime.h>
#include <mma.h>
#include <cstdint>

using namespace nvcuda;

constexpr int B   = 256;
constexpr int T   = 256;
constexpr int D   = 72;
constexpr int HID = 512;
constexpr int H   = 1024;
constexpr int H3  = 3 * H;
constexpr int P   = 10;
constexpr int BT  = B * T;

// ----------------------------------------------------------------------------
// Device scratch
// ----------------------------------------------------------------------------
__device__ float g_buf1  [(size_t)BT * HID];
__device__ float g_latent[(size_t)BT * H];
__device__ float g_xp    [(size_t)BT * H3];   // [T, B, 3H]
__device__ float g_eout  [(size_t)BT * H];    // [T, B, H]
__device__ float g_hb0   [B * H];             // hF fragment-order
__device__ float g_hb1   [B * H];
__device__ float g_logits[BT];
__device__ float g_lpart [4 * BT];
__device__ float g_wts   [BT];
__device__ float g_hs    [B * H];
__device__ float g_hs2   [B * H];
__device__ float g_hrow  [B * H];
__device__ float g_p0    [B * D];
__device__ float g_d1    [B * HID];
__device__ float g_dinp  [B * H];
__device__ float g_gi    [B * H3];
__device__ float g_l1    [B * HID];
constexpr int WSW_TILE = 128 * 6 * 64;
__device__ float g_wsw_enc[(size_t)64 * WSW_TILE];
__device__ float g_wsw_dec[(size_t)64 * WSW_TILE];
constexpr size_t WT_P2L1   = 0;
constexpr size_t WT_P2L2   = WT_P2L1 + 512 * 72;
constexpr size_t WT_ENCWIH = WT_P2L2 + 1024 * 512;
constexpr size_t WT_L2S1   = WT_ENCWIH + (size_t)3072 * 1024;
constexpr size_t WT_DECWIH = WT_L2S1 + 512 * 1024;
constexpr size_t WT_L2P1   = WT_DECWIH + (size_t)3072 * 1024;
constexpr size_t WT_TOTAL  = WT_L2P1 + 512 * 1024;
__device__ float g_wtf[WT_TOTAL];

__device__ __forceinline__ size_t hf_idx(int b, int k) {
    return ((((size_t)(k >> 3) * 16 + (b >> 4)) * 32 +
             ((b & 7) * 4 + (k & 3))) << 2) +
           (((b >> 3) & 1) + 2 * ((k >> 2) & 1));
}

__device__ __forceinline__ float sigf(float x) { return 1.f / (1.f + expf(-x)); }

__device__ __forceinline__ uint32_t f2tf32(float x) {
    uint32_t r;
    asm("cvt.rna.tf32.f32 %0, %1;" : "=r"(r) : "f"(x));
    return r;
}

__device__ __forceinline__ void mma_tf32(float d[4], const uint32_t a[4],
                                         uint32_t b0, uint32_t b1) {
    asm volatile(
        "mma.sync.aligned.m16n8k8.row.col.f32.tf32.tf32.f32 "
        "{%0,%1,%2,%3}, {%4,%5,%6,%7}, {%8,%9}, {%0,%1,%2,%3};"
        : "+f"(d[0]), "+f"(d[1]), "+f"(d[2]), "+f"(d[3])
        : "r"(a[0]), "r"(a[1]), "r"(a[2]), "r"(a[3]), "r"(b0), "r"(b1));
}

__device__ __forceinline__ uint32_t smem_u32(const void* p) {
    return (uint32_t)__cvta_generic_to_shared(p);
}
__device__ __forceinline__ void cp16(uint32_t dst, const void* src) {
    asm volatile("cp.async.ca.shared.global [%0], [%1], 16;" :: "r"(dst), "l"(src));
}

// ----------------------------------------------------------------------------
// Merged tf32 weight rounding (6 segments -> g_wtf)
// ----------------------------------------------------------------------------
constexpr int CN0 = 512 * 72 / 4;
constexpr int CN1 = CN0 + 1024 * 512 / 4;
constexpr int CN2 = CN1 + 3072 * 1024 / 4;
constexpr int CN3 = CN2 + 512 * 1024 / 4;
constexpr int CN4 = CN3 + 3072 * 1024 / 4;
constexpr int CN5 = CN4 + 512 * 1024 / 4;

__global__ void cvt_all(const float* __restrict__ s0, const float* __restrict__ s1,
                        const float* __restrict__ s2, const float* __restrict__ s3,
                        const float* __restrict__ s4, const float* __restrict__ s5,
                        float* __restrict__ dst)
{
    int i = blockIdx.x * blockDim.x + threadIdx.x;
    if (i >= CN5) return;
    const float* src; int off;
    if      (i < CN0) { src = s0; off = i; }
    else if (i < CN1) { src = s1; off = i - CN0; }
    else if (i < CN2) { src = s2; off = i - CN1; }
    else if (i < CN3) { src = s3; off = i - CN2; }
    else if (i < CN4) { src = s4; off = i - CN3; }
    else              { src = s5; off = i - CN4; }
    float4 v = reinterpret_cast<const float4*>(src)[off];
    v.x = __uint_as_float(f2tf32(v.x));
    v.y = __uint_as_float(f2tf32(v.y));
    v.z = __uint_as_float(f2tf32(v.z));
    v.w = __uint_as_float(f2tf32(v.w));
    reinterpret_cast<float4*>(dst)[i] = v;
}

// ----------------------------------------------------------------------------
// GEMM v3 (128x128, 256 thr, 2 CTAs/SM, 3-stage cp.async) — proven.
// ----------------------------------------------------------------------------
#define BM 128
#define BN 128
#define BK 32
constexpr int GLDS = BK + 4;
constexpr int STG  = (BM + BN) * GLDS;
constexpr int GM_SMEM_BYTES = 3 * STG * 4;

__device__ __forceinline__ void cp_stage(
    float* st, const float* __restrict__ A, int lda,
    const float* __restrict__ W, int K,
    int bm, int bn, int kk, int tid)
{
#pragma unroll
    for (int i = 0; i < 4; i++) {
        int idx = tid + i * 256;
        int r   = idx >> 3;
        int c4  = (idx & 7) * 4;
        int gk  = kk + c4;
        float* da = st + r * GLDS + c4;
        float* db = st + (BM + r) * GLDS + c4;
        const float* sa = A + (size_t)(bm + r) * lda + gk;
        const float* sb = W + (size_t)(bn + r) * K + gk;
        if (gk + 4 <= K) {
            cp16(smem_u32(da), sa);
            cp16(smem_u32(db), sb);
        } else {
            float4 va, vb;
            va.x = (gk + 0 < K) ? sa[0] : 0.f;  vb.x = (gk + 0 < K) ? sb[0] : 0.f;
            va.y = (gk + 1 < K) ? sa[1] : 0.f;  vb.y = (gk + 1 < K) ? sb[1] : 0.f;
            va.z = (gk + 2 < K) ? sa[2] : 0.f;  vb.z = (gk + 2 < K) ? sb[2] : 0.f;
            va.w = (gk + 3 < K) ? sa[3] : 0.f;  vb.w = (gk + 3 < K) ? sb[3] : 0.f;
            *reinterpret_cast<float4*>(da) = va;
            *reinterpret_cast<float4*>(db) = vb;
        }
    }
    asm volatile("cp.async.commit_group;");
}

__global__ void __launch_bounds__(256, 2)
gemm_tf32_v3(const float* __restrict__ A, int lda,
             const float* __restrict__ W,
             const float* __restrict__ bias,
             float* __restrict__ C, int ldc,
             int M, int N, int K, int act, int permute_bt,
             const float* __restrict__ lw, float* __restrict__ lpart)
{
    extern __shared__ float sm[];
    float* Cs = sm;

    const int bm  = blockIdx.y * BM;
    const int bn  = blockIdx.x * BN;
    const int tid = threadIdx.x;
    const int w   = tid >> 5;
    const int wm  = w & 3;
    const int wn  = w >> 2;

    wmma::fragment<wmma::accumulator, 16, 16, 8, float> c[2][4];
#pragma unroll
    for (int i = 0; i < 2; i++)
#pragma unroll
        for (int j = 0; j < 4; j++)
            wmma::fill_fragment(c[i][j], 0.0f);

    const int niter = (K + BK - 1) / BK;

    cp_stage(sm, A, lda, W, K, bm, bn, 0, tid);
    if (niter > 1) cp_stage(sm + STG, A, lda, W, K, bm, bn, BK, tid);

    for (int it = 0; it < niter; it++) {
        if (it + 1 < niter) asm volatile("cp.async.wait_group 1;");
        else                asm volatile("cp.async.wait_group 0;");
        __syncthreads();
        if (it + 2 < niter)
            cp_stage(sm + ((it + 2) % 3) * STG, A, lda, W, K, bm, bn,
                     (it + 2) * BK, tid);

        const float* As = sm + (it % 3) * STG;
        const float* Bs = As + BM * GLDS;
#pragma unroll
        for (int ks = 0; ks < 4; ks++) {
            wmma::fragment<wmma::matrix_a, 16, 16, 8, wmma::precision::tf32, wmma::row_major> af[2];
            wmma::fragment<wmma::matrix_b, 16, 16, 8, wmma::precision::tf32, wmma::col_major> bf[4];
#pragma unroll
            for (int i = 0; i < 2; i++) {
                wmma::load_matrix_sync(af[i], As + (wm * 32 + i * 16) * GLDS + ks * 8, GLDS);
#pragma unroll
                for (int e = 0; e < af[i].num_elements; e++)
                    af[i].x[e] = wmma::__float_to_tf32(af[i].x[e]);
            }
#pragma unroll
            for (int j = 0; j < 4; j++)
                wmma::load_matrix_sync(bf[j], Bs + (wn * 64 + j * 16) * GLDS + ks * 8, GLDS);
#pragma unroll
            for (int i = 0; i < 2; i++)
#pragma unroll
                for (int j = 0; j < 4; j++)
                    wmma::mma_sync(c[i][j], af[i], bf[j], c[i][j]);
        }
    }

    __syncthreads();
#pragma unroll
    for (int i = 0; i < 2; i++)
#pragma unroll
        for (int j = 0; j < 4; j++)
            wmma::store_matrix_sync(Cs + (wm * 32 + i * 16) * (BN + 4) + wn * 64 + j * 16,
                                    c[i][j], BN + 4, wmma::mem_row_major);
    __syncthreads();

#pragma unroll
    for (int i = 0; i < 16; i++) {
        int idx4 = tid + i * 256;
        int r    = idx4 >> 5;
        int c4   = (idx4 & 31) * 4;
        float4 v = *reinterpret_cast<const float4*>(Cs + r * (BN + 4) + c4);
        if (bias) {
            float4 bv = *reinterpret_cast<const float4*>(bias + bn + c4);
            v.x += bv.x; v.y += bv.y; v.z += bv.z; v.w += bv.w;
        }
        if (act == 1) {
            v.x = fmaxf(v.x, 0.f); v.y = fmaxf(v.y, 0.f);
            v.z = fmaxf(v.z, 0.f); v.w = fmaxf(v.w, 0.f);
        }
        int gr   = bm + r;
        int orow = permute_bt ? (((gr & 255) << 8) | (gr >> 8)) : gr;
        if (!lpart) {
            *reinterpret_cast<float4*>(C + (size_t)orow * ldc + bn + c4) = v;
        } else {
            float4 wv4 = *reinterpret_cast<const float4*>(lw + bn + c4);
            float d = v.x * wv4.x + v.y * wv4.y + v.z * wv4.z + v.w * wv4.w;
#pragma unroll
            for (int o = 16; o > 0; o >>= 1)
                d += __shfl_xor_sync(0xffffffffu, d, o);
            if ((tid & 31) == 0)
                lpart[(size_t)(bn >> 7) * M + orow] = d;
        }
    }
}

__global__ void logits_reduce(const float* __restrict__ lpart,
                              const float* __restrict__ b2,
                              float* __restrict__ logits)
{
    int i = blockIdx.x * blockDim.x + threadIdx.x;
    if (i >= BT) return;
    logits[i] = lpart[i] + lpart[BT + i] + lpart[2 * BT + i] +
                lpart[3 * BT + i] + b2[0];
}

// ----------------------------------------------------------------------------
// Whh pre-swizzle (unchanged)
// ----------------------------------------------------------------------------
__global__ void swizzle_whh(const float* __restrict__ whh, float* __restrict__ wsw)
{
    int nt = blockIdx.x;
    int n0 = nt * 16;
    for (int i = threadIdx.x; i < 128 * 6 * 32; i += blockDim.x) {
        int lane  = i & 31;
        int pos   = i >> 5;
        int kstep = pos / 6;
        int g2    = pos % 6;
        int g  = g2 >> 1;
        int nj = g2 & 1;
        int q = lane >> 2, t = lane & 3;
        const float* src = whh + (size_t)(g * H + n0 + nj * 8 + q) * H + kstep * 8 + t;
        float2 v;
        v.x = __uint_as_float(f2tf32(src[0]));
        v.y = __uint_as_float(f2tf32(src[4]));
        *reinterpret_cast<float2*>(wsw + (size_t)nt * WSW_TILE + (size_t)pos * 64 + lane * 2) = v;
    }
}

// ----------------------------------------------------------------------------
// Fused single GRU step v7 (proven)
// ----------------------------------------------------------------------------
constexpr int RC_LDA     = 20;
constexpr int RC_GFLOATS = 3 * 128 * RC_LDA;
constexpr int RC_SMEM_BYTES = RC_GFLOATS * 4;

__global__ void __launch_bounds__(512, 1)
gru_step(const float* __restrict__ wsw, const float* __restrict__ bhh,
         const float* __restrict__ gi, size_t gi_bstride,
         const float* __restrict__ hF_read, float* __restrict__ hF_write,
         float* __restrict__ eout_t, size_t eout_bstride,
         float* __restrict__ hrow_write)
{
    extern __shared__ float Gsm[];

    const int tid  = threadIdx.x;
    const int lane = tid & 31;
    const int w    = tid >> 5;
    const int grp  = w >> 2;
    const int wm   = w & 3;
    const int nt   = blockIdx.x & 63;
    const int bt   = blockIdx.x >> 6;
    const int b0   = bt * 128;
    const int n0   = nt * 16;

    const float2* wg  = reinterpret_cast<const float2*>(wsw + (size_t)nt * WSW_TILE);
    const float4* hF4 = reinterpret_cast<const float4*>(hF_read);
    const int k8base  = grp * 32;
    const int mbb     = bt * 8 + wm * 2;

    float acc[2][3][2][4];
#pragma unroll
    for (int mh = 0; mh < 2; mh++)
#pragma unroll
        for (int g = 0; g < 3; g++)
#pragma unroll
            for (int nj = 0; nj < 2; nj++)
#pragma unroll
                for (int e = 0; e < 4; e++) acc[mh][g][nj][e] = 0.f;

    float4 pf[2];
    float2 wv[6];
#pragma unroll
    for (int mh = 0; mh < 2; mh++)
        pf[mh] = hF4[((size_t)k8base * 16 + mbb + mh) * 32 + lane];
#pragma unroll
    for (int j = 0; j < 6; j++)
        wv[j] = wg[((size_t)(k8base * 6) + j) * 32 + lane];

    for (int c = 0; c < 32; c++) {
        uint32_t A[2][4];
#pragma unroll
        for (int mh = 0; mh < 2; mh++) {
            A[mh][0] = f2tf32(pf[mh].x);
            A[mh][1] = f2tf32(pf[mh].y);
            A[mh][2] = f2tf32(pf[mh].z);
            A[mh][3] = f2tf32(pf[mh].w);
        }
        uint32_t bw0[6], bw1[6];
#pragma unroll
        for (int j = 0; j < 6; j++) {
            bw0[j] = __float_as_uint(wv[j].x);
            bw1[j] = __float_as_uint(wv[j].y);
        }

        if (c < 31) {
#pragma unroll
            for (int mh = 0; mh < 2; mh++)
                pf[mh] = hF4[((size_t)(k8base + c + 1) * 16 + mbb + mh) * 32 + lane];
#pragma unroll
            for (int j = 0; j < 6; j++)
                wv[j] = wg[((size_t)((k8base + c + 1) * 6) + j) * 32 + lane];
        }

#pragma unroll
        for (int g = 0; g < 3; g++) {
#pragma unroll
            for (int nj = 0; nj < 2; nj++) {
                int j = g * 2 + nj;
                mma_tf32(acc[0][g][nj], A[0], bw0[j], bw1[j]);
                mma_tf32(acc[1][g][nj], A[1], bw0[j], bw1[j]);
            }
        }
    }

    const int q = lane >> 2;
    const int t = lane & 3;
    const int ccol = 2 * t;
#pragma unroll
    for (int pass = 3; pass >= 0; pass--) {
        if (grp == pass) {
#pragma unroll
            for (int mh = 0; mh < 2; mh++)
#pragma unroll
                for (int g = 0; g < 3; g++)
#pragma unroll
                    for (int nj = 0; nj < 2; nj++) {
                        int row = wm * 32 + mh * 16 + q;
                        float* b0p = Gsm + (g * 128 + row) * RC_LDA + nj * 8 + ccol;
                        float* b1p = Gsm + (g * 128 + row + 8) * RC_LDA + nj * 8 + ccol;
                        if (pass == 3) {
                            b0p[0] = acc[mh][g][nj][0];
                            b0p[1] = acc[mh][g][nj][1];
                            b1p[0] = acc[mh][g][nj][2];
                            b1p[1] = acc[mh][g][nj][3];
                        } else {
                            b0p[0] += acc[mh][g][nj][0];
                            b0p[1] += acc[mh][g][nj][1];
                            b1p[0] += acc[mh][g][nj][2];
                            b1p[1] += acc[mh][g][nj][3];
                        }
                    }
        }
        __syncthreads();
    }

    {
        const int k8l  = tid >> 8;
        const int mbl  = (tid >> 5) & 7;
        const int ln   = tid & 31;
        const int bq   = ln >> 2;
        const int nq   = ln & 3;
        const size_t fidx = ((size_t)(nt * 2 + k8l) * 16 + (bt * 8 + mbl)) * 32 + ln;

        float4 hv4 = hF4[fidx];
        float outv[4];
#pragma unroll
        for (int kh = 0; kh < 2; kh++) {
#pragma unroll
            for (int rh = 0; rh < 2; rh++) {
                int reg = rh + 2 * kh;
                int bl  = mbl * 16 + bq + 8 * rh;
                int nl  = k8l * 8 + nq + 4 * kh;
                int b   = b0 + bl;
                int nc  = n0 + nl;
                float hr = Gsm[(0 * 128 + bl) * RC_LDA + nl] + bhh[nc];
                float hz = Gsm[(1 * 128 + bl) * RC_LDA + nl] + bhh[H + nc];
                float hn = Gsm[(2 * 128 + bl) * RC_LDA + nl] + bhh[2 * H + nc];
                const float* gib = gi + (size_t)b * gi_bstride;
                float ir = gib[nc], iz = gib[H + nc], in_ = gib[2 * H + nc];
                float r  = sigf(ir + hr);
                float z  = sigf(iz + hz);
                float nn = tanhf(in_ + r * hn);
                float hv = (&hv4.x)[reg];
                float hnew = (1.f - z) * nn + z * hv;
                outv[reg] = hnew;
                if (eout_t) eout_t[(size_t)b * eout_bstride + nc] = hnew;
                if (hrow_write) hrow_write[(size_t)b * H + nc] = hnew;
            }
        }
        float4 o4 = make_float4(outv[0], outv[1], outv[2], outv[3]);
        reinterpret_cast<float4*>(hF_write)[fidx] = o4;
    }
}

// ----------------------------------------------------------------------------
// Small kernels
// ----------------------------------------------------------------------------
__global__ void softmax_kernel(const float* __restrict__ logits,
                               float* __restrict__ wts)
{
    __shared__ float sdata[T];
    int b = blockIdx.x, t = threadIdx.x;
    float v = logits[t * B + b];
    sdata[t] = v;
    __syncthreads();
    for (int s = T / 2; s > 0; s >>= 1) {
        if (t < s) sdata[t] = fmaxf(sdata[t], sdata[t + s]);
        __syncthreads();
    }
    float mx = sdata[0];
    __syncthreads();
    float e = expf(v - mx);
    sdata[t] = e;
    __syncthreads();
    for (int s = T / 2; s > 0; s >>= 1) {
        if (t < s) sdata[t] += sdata[t + s];
        __syncthreads();
    }
    wts[t * B + b] = e / sdata[0];
}

__global__ void pool_kernel(const float* __restrict__ eout,
                            const float* __restrict__ wts,
                            float* __restrict__ hsF,
                            float* __restrict__ rep_out)
{
    __shared__ float w[T];
    int b = blockIdx.x, tid = threadIdx.x;
    w[tid] = wts[tid * B + b];
    __syncthreads();
    for (int h0 = tid; h0 < H; h0 += blockDim.x) {
        const float* base = eout + (size_t)b * H + h0;
        float acc = 0.f;
#pragma unroll 4
        for (int t = 0; t < T; t++) acc += w[t] * base[(size_t)t * B * H];
        hsF[hf_idx(b, h0)] = acc;
        if (rep_out) rep_out[b * H + h0] = acc;
    }
}

__global__ void gather_last(const float* __restrict__ x, float* __restrict__ p0)
{
    int idx = blockIdx.x * blockDim.x + threadIdx.x;
    if (idx >= B * D) return;
    int b = idx / D, dd = idx % D;
    p0[idx] = x[((size_t)b * T + (T - 1)) * D + dd];
}

// fp32 pred head (restored from round 12 — faster than a 2-CTA GEMM and
// keeps the final layer in fp32, restoring rel_err to 5.14e-4)
__global__ void pred_kernel(const float* __restrict__ l1,
                            const float* __restrict__ w,
                            const float* __restrict__ bias,
                            float* __restrict__ out, int ldc)
{
    __shared__ float row[HID];
    int m = blockIdx.x;
    for (int k = threadIdx.x; k < HID; k += blockDim.x)
        row[k] = l1[(size_t)m * HID + k];
    __syncthreads();
    int n = threadIdx.x;
    if (n < D) {
        const float* wr = w + (size_t)n * HID;
        float acc = bias[n];
        for (int k = 0; k < HID; k++) acc += row[k] * wr[k];
        out[(size_t)m * ldc + n] = acc;
    }
}

// ----------------------------------------------------------------------------
// Host driver
// ----------------------------------------------------------------------------
static inline void launch_gemm(const float* A, int lda, const float* W,
                               const float* bias, float* C, int ldc,
                               int M, int N, int K, int act, int permute_bt = 0,
                               const float* lw = nullptr, float* lpart = nullptr)
{
    dim3 grid(N / BN, M / BM);
    gemm_tf32_v3<<<grid, 256, GM_SMEM_BYTES>>>(A, lda, W, bias, C, ldc, M, N, K,
                                               act, permute_bt, lw, lpart);
}

extern "C" void kernel_launch(void* const* d_in, const int* in_sizes, int n_in,
                              void* d_out, int out_size)
{
    const float* x       = (const float*)d_in[0];
    const float* p2l_w1  = (const float*)d_in[2];
    const float* p2l_b1  = (const float*)d_in[3];
    const float* p2l_w2  = (const float*)d_in[4];
    const float* p2l_b2  = (const float*)d_in[5];
    const float* enc_wih = (const float*)d_in[6];
    const float* enc_whh = (const float*)d_in[7];
    const float* enc_bih = (const float*)d_in[8];
    const float* enc_bhh = (const float*)d_in[9];
    const float* dec_wih = (const float*)d_in[10];
    const float* dec_whh = (const float*)d_in[11];
    const float* dec_bih = (const float*)d_in[12];
    const float* dec_bhh = (const float*)d_in[13];
    const float* l2p_w1  = (const float*)d_in[14];
    const float* l2p_b1  = (const float*)d_in[15];
    const float* l2p_w2  = (const float*)d_in[16];
    const float* l2p_b2  = (const float*)d_in[17];
    const float* l2s_w1  = (const float*)d_in[18];
    const float* l2s_b1  = (const float*)d_in[19];
    const float* l2s_w2  = (const float*)d_in[20];
    const float* l2s_b2  = (const float*)d_in[21];

    float* out = (float*)d_out;
    const int PREDS = B * P * D;
    float* rep_out = (out_size >= PREDS + B * H) ? (out + PREDS) : nullptr;

    float *p_buf1, *p_latent, *p_xp, *p_eout, *p_hb0, *p_hb1, *p_logits,
          *p_lpart, *p_wts, *p_hs, *p_hs2, *p_hrow, *p_p0, *p_d1, *p_dinp,
          *p_gi, *p_l1, *p_wsw_enc, *p_wsw_dec, *p_wtf;
    void* tmp;
#define SYM(dst, sym) cudaGetSymbolAddress(&tmp, sym); dst = (decltype(dst))tmp;
    SYM(p_buf1, g_buf1)   SYM(p_latent, g_latent) SYM(p_xp, g_xp)
    SYM(p_eout, g_eout)   SYM(p_hb0, g_hb0)       SYM(p_hb1, g_hb1)
    SYM(p_logits, g_logits) SYM(p_lpart, g_lpart) SYM(p_wts, g_wts)
    SYM(p_hs, g_hs)       SYM(p_hs2, g_hs2)       SYM(p_hrow, g_hrow)
    SYM(p_p0, g_p0)       SYM(p_d1, g_d1)         SYM(p_dinp, g_dinp)
    SYM(p_gi, g_gi)       SYM(p_l1, g_l1)         SYM(p_wsw_enc, g_wsw_enc)
    SYM(p_wsw_dec, g_wsw_dec) SYM(p_wtf, g_wtf)
#undef SYM

    float* w_p2l1   = p_wtf + WT_P2L1;
    float* w_p2l2   = p_wtf + WT_P2L2;
    float* w_encwih = p_wtf + WT_ENCWIH;
    float* w_l2s1   = p_wtf + WT_L2S1;
    float* w_decwih = p_wtf + WT_DECWIH;
    float* w_l2p1   = p_wtf + WT_L2P1;

    cudaFuncSetAttribute(gru_step, cudaFuncAttributeMaxDynamicSharedMemorySize,
                         RC_SMEM_BYTES);
    cudaFuncSetAttribute(gemm_tf32_v3, cudaFuncAttributeMaxDynamicSharedMemorySize,
                         GM_SMEM_BYTES);

    // ---- one-time weight preprocessing (EXACTLY 3 launches so ncu -s 5
    //      samples the xp GEMM at launch index 5) ----
    swizzle_whh<<<64, 256>>>(enc_whh, p_wsw_enc);
    swizzle_whh<<<64, 256>>>(dec_whh, p_wsw_dec);
    cvt_all<<<(CN5 + 255) / 256, 256>>>(p2l_w1, p2l_w2, enc_wih, l2s_w1,
                                        dec_wih, l2p_w1, p_wtf);

    // ---- par2lat(x)  (launches 3, 4) ----
    launch_gemm(x, D, w_p2l1, p2l_b1, p_buf1, HID, BT, HID, D, 1);
    launch_gemm(p_buf1, HID, w_p2l2, p2l_b2, p_latent, H, BT, H, HID, 1);

    // ---- xp = latent @ enc_wih^T + enc_bih, t-major [T, B, 3H]  (launch 5) ----
    launch_gemm(p_latent, H, w_encwih, enc_bih, p_xp, H3, BT, H3, H, 0, 1);

    // ---- encoder recurrence ----
    cudaMemsetAsync(p_hb0, 0, (size_t)B * H * sizeof(float));
    {
        float* hr = p_hb0;
        float* hw = p_hb1;
        for (int t = 0; t < T; t++) {
            gru_step<<<128, 512, RC_SMEM_BYTES>>>(
                p_wsw_enc, enc_bhh,
                p_xp + (size_t)t * B * H3, (size_t)H3,
                hr, hw,
                p_eout + (size_t)t * B * H, (size_t)H,
                nullptr);
            float* t2 = hr; hr = hw; hw = t2;
        }
    }

    // ---- attention pooling: fused s1-GEMM + logits dot ----
    launch_gemm(p_eout, H, w_l2s1, l2s_b1, nullptr, HID, BT, HID, H, 1, 0,
                l2s_w2, p_lpart);
    logits_reduce<<<BT / 256, 256>>>(p_lpart, l2s_b2, p_logits);
    softmax_kernel<<<B, T>>>(p_logits, p_wts);
    pool_kernel<<<B, 256>>>(p_eout, p_wts, p_hs, rep_out);

    // ---- autoregressive decode ----
    gather_last<<<(B * D + 255) / 256, 256>>>(x, p_p0);
    float* hF_read  = p_hs;
    float* hF_write = p_hs2;
    for (int s = 0; s < P; s++) {
        const float* pin = (s == 0) ? p_p0 : (out + (size_t)(s - 1) * D);
        int plda = (s == 0) ? D : (P * D);
        launch_gemm(pin, plda, w_p2l1, p2l_b1, p_d1, HID, B, HID, D, 1);
        launch_gemm(p_d1, HID, w_p2l2, p2l_b2, p_dinp, H, B, H, HID, 1);
        launch_gemm(p_dinp, H, w_decwih, dec_bih, p_gi, H3, B, H3, H, 0);
        gru_step<<<128, 512, RC_SMEM_BYTES>>>(
            p_wsw_dec, dec_bhh, p_gi, (size_t)H3,
            hF_read, hF_write, nullptr, 0, p_hrow);
        launch_gemm(p_hrow, H, w_l2p1, l2p_b1, p_l1, HID, B, HID, H, 1);
        pred_kernel<<<B, 128>>>(p_l1, l2p_w2, l2p_b2,
                                out + (size_t)s * D, P * D);
        float* t2 = hF_read; hF_read = hF_write; hF_write = t2;
    }
}

// round 16
// speedup vs baseline: 1.0664x; 1.0099x over previous
#include <cuda_runtime.h>
#include <mma.h>
#include <cstdint>

using namespace nvcuda;

constexpr int B   = 256;
constexpr int T   = 256;
constexpr int D   = 72;
constexpr int HID = 512;
constexpr int H   = 1024;
constexpr int H3  = 3 * H;
constexpr int P   = 10;
constexpr int BT  = B * T;

// ----------------------------------------------------------------------------
// Device scratch
// ----------------------------------------------------------------------------
__device__ float g_buf1  [(size_t)BT * HID];
__device__ float g_latent[(size_t)BT * H];
__device__ float g_xp    [(size_t)BT * H3];   // gate-tile layout [T][64][3][256][16]
__device__ float g_eout  [(size_t)BT * H];    // [T, B, H]
__device__ float g_hb0   [B * H];             // hF fragment-order
__device__ float g_hb1   [B * H];
__device__ float g_logits[BT];
__device__ float g_lpart [4 * BT];
__device__ float g_wts   [BT];
__device__ float g_hs    [B * H];
__device__ float g_hs2   [B * H];
__device__ float g_hrow  [B * H];
__device__ float g_p0    [B * D];
__device__ float g_d1    [B * HID];
__device__ float g_dinp  [B * H];
__device__ float g_gi    [B * H3];            // gate-tile layout [64][3][256][16]
__device__ float g_l1    [B * HID];
constexpr int WSW_TILE = 128 * 6 * 64;
__device__ float g_wsw_enc[(size_t)64 * WSW_TILE];
__device__ float g_wsw_dec[(size_t)64 * WSW_TILE];
constexpr size_t WT_P2L1   = 0;
constexpr size_t WT_P2L2   = WT_P2L1 + 512 * 72;
constexpr size_t WT_ENCWIH = WT_P2L2 + 1024 * 512;
constexpr size_t WT_L2S1   = WT_ENCWIH + (size_t)3072 * 1024;
constexpr size_t WT_DECWIH = WT_L2S1 + 512 * 1024;
constexpr size_t WT_L2P1   = WT_DECWIH + (size_t)3072 * 1024;
constexpr size_t WT_TOTAL  = WT_L2P1 + 512 * 1024;
__device__ float g_wtf[WT_TOTAL];

__device__ __forceinline__ size_t hf_idx(int b, int k) {
    return ((((size_t)(k >> 3) * 16 + (b >> 4)) * 32 +
             ((b & 7) * 4 + (k & 3))) << 2) +
           (((b >> 3) & 1) + 2 * ((k >> 2) & 1));
}

__device__ __forceinline__ float sigf(float x) { return 1.f / (1.f + expf(-x)); }

__device__ __forceinline__ uint32_t f2tf32(float x) {
    uint32_t r;
    asm("cvt.rna.tf32.f32 %0, %1;" : "=r"(r) : "f"(x));
    return r;
}

__device__ __forceinline__ void mma_tf32(float d[4], const uint32_t a[4],
                                         uint32_t b0, uint32_t b1) {
    asm volatile(
        "mma.sync.aligned.m16n8k8.row.col.f32.tf32.tf32.f32 "
        "{%0,%1,%2,%3}, {%4,%5,%6,%7}, {%8,%9}, {%0,%1,%2,%3};"
        : "+f"(d[0]), "+f"(d[1]), "+f"(d[2]), "+f"(d[3])
        : "r"(a[0]), "r"(a[1]), "r"(a[2]), "r"(a[3]), "r"(b0), "r"(b1));
}

__device__ __forceinline__ uint32_t smem_u32(const void* p) {
    return (uint32_t)__cvta_generic_to_shared(p);
}
__device__ __forceinline__ void cp16(uint32_t dst, const void* src) {
    asm volatile("cp.async.ca.shared.global [%0], [%1], 16;" :: "r"(dst), "l"(src));
}

// ----------------------------------------------------------------------------
// Merged tf32 weight rounding (6 segments -> g_wtf)
// ----------------------------------------------------------------------------
constexpr int CN0 = 512 * 72 / 4;
constexpr int CN1 = CN0 + 1024 * 512 / 4;
constexpr int CN2 = CN1 + 3072 * 1024 / 4;
constexpr int CN3 = CN2 + 512 * 1024 / 4;
constexpr int CN4 = CN3 + 3072 * 1024 / 4;
constexpr int CN5 = CN4 + 512 * 1024 / 4;

__global__ void cvt_all(const float* __restrict__ s0, const float* __restrict__ s1,
                        const float* __restrict__ s2, const float* __restrict__ s3,
                        const float* __restrict__ s4, const float* __restrict__ s5,
                        float* __restrict__ dst)
{
    int i = blockIdx.x * blockDim.x + threadIdx.x;
    if (i >= CN5) return;
    const float* src; int off;
    if      (i < CN0) { src = s0; off = i; }
    else if (i < CN1) { src = s1; off = i - CN0; }
    else if (i < CN2) { src = s2; off = i - CN1; }
    else if (i < CN3) { src = s3; off = i - CN2; }
    else if (i < CN4) { src = s4; off = i - CN3; }
    else              { src = s5; off = i - CN4; }
    float4 v = reinterpret_cast<const float4*>(src)[off];
    v.x = __uint_as_float(f2tf32(v.x));
    v.y = __uint_as_float(f2tf32(v.y));
    v.z = __uint_as_float(f2tf32(v.z));
    v.w = __uint_as_float(f2tf32(v.w));
    reinterpret_cast<float4*>(dst)[i] = v;
}

// ----------------------------------------------------------------------------
// GEMM v3 (128x128, 256 thr, 2 CTAs/SM, 3-stage cp.async) — proven.
// gate_tile: 0 = normal row store; 1 = rows are b*T+t, store to
// [t][nt][g][b][16]; 2 = rows are b (decode), store to [nt][g][b][16].
// ----------------------------------------------------------------------------
#define BM 128
#define BN 128
#define BK 32
constexpr int GLDS = BK + 4;
constexpr int STG  = (BM + BN) * GLDS;
constexpr int GM_SMEM_BYTES = 3 * STG * 4;

__device__ __forceinline__ void cp_stage(
    float* st, const float* __restrict__ A, int lda,
    const float* __restrict__ W, int K,
    int bm, int bn, int kk, int tid)
{
#pragma unroll
    for (int i = 0; i < 4; i++) {
        int idx = tid + i * 256;
        int r   = idx >> 3;
        int c4  = (idx & 7) * 4;
        int gk  = kk + c4;
        float* da = st + r * GLDS + c4;
        float* db = st + (BM + r) * GLDS + c4;
        const float* sa = A + (size_t)(bm + r) * lda + gk;
        const float* sb = W + (size_t)(bn + r) * K + gk;
        if (gk + 4 <= K) {
            cp16(smem_u32(da), sa);
            cp16(smem_u32(db), sb);
        } else {
            float4 va, vb;
            va.x = (gk + 0 < K) ? sa[0] : 0.f;  vb.x = (gk + 0 < K) ? sb[0] : 0.f;
            va.y = (gk + 1 < K) ? sa[1] : 0.f;  vb.y = (gk + 1 < K) ? sb[1] : 0.f;
            va.z = (gk + 2 < K) ? sa[2] : 0.f;  vb.z = (gk + 2 < K) ? sb[2] : 0.f;
            va.w = (gk + 3 < K) ? sa[3] : 0.f;  vb.w = (gk + 3 < K) ? sb[3] : 0.f;
            *reinterpret_cast<float4*>(da) = va;
            *reinterpret_cast<float4*>(db) = vb;
        }
    }
    asm volatile("cp.async.commit_group;");
}

__global__ void __launch_bounds__(256, 2)
gemm_tf32_v3(const float* __restrict__ A, int lda,
             const float* __restrict__ W,
             const float* __restrict__ bias,
             float* __restrict__ C, int ldc,
             int M, int N, int K, int act, int gate_tile,
             const float* __restrict__ lw, float* __restrict__ lpart)
{
    extern __shared__ float sm[];
    float* Cs = sm;

    const int bm  = blockIdx.y * BM;
    const int bn  = blockIdx.x * BN;
    const int tid = threadIdx.x;
    const int w   = tid >> 5;
    const int wm  = w & 3;
    const int wn  = w >> 2;

    wmma::fragment<wmma::accumulator, 16, 16, 8, float> c[2][4];
#pragma unroll
    for (int i = 0; i < 2; i++)
#pragma unroll
        for (int j = 0; j < 4; j++)
            wmma::fill_fragment(c[i][j], 0.0f);

    const int niter = (K + BK - 1) / BK;

    cp_stage(sm, A, lda, W, K, bm, bn, 0, tid);
    if (niter > 1) cp_stage(sm + STG, A, lda, W, K, bm, bn, BK, tid);

    for (int it = 0; it < niter; it++) {
        if (it + 1 < niter) asm volatile("cp.async.wait_group 1;");
        else                asm volatile("cp.async.wait_group 0;");
        __syncthreads();
        if (it + 2 < niter)
            cp_stage(sm + ((it + 2) % 3) * STG, A, lda, W, K, bm, bn,
                     (it + 2) * BK, tid);

        const float* As = sm + (it % 3) * STG;
        const float* Bs = As + BM * GLDS;
#pragma unroll
        for (int ks = 0; ks < 4; ks++) {
            wmma::fragment<wmma::matrix_a, 16, 16, 8, wmma::precision::tf32, wmma::row_major> af[2];
            wmma::fragment<wmma::matrix_b, 16, 16, 8, wmma::precision::tf32, wmma::col_major> bf[4];
#pragma unroll
            for (int i = 0; i < 2; i++) {
                wmma::load_matrix_sync(af[i], As + (wm * 32 + i * 16) * GLDS + ks * 8, GLDS);
#pragma unroll
                for (int e = 0; e < af[i].num_elements; e++)
                    af[i].x[e] = wmma::__float_to_tf32(af[i].x[e]);
            }
#pragma unroll
            for (int j = 0; j < 4; j++)
                wmma::load_matrix_sync(bf[j], Bs + (wn * 64 + j * 16) * GLDS + ks * 8, GLDS);
#pragma unroll
            for (int i = 0; i < 2; i++)
#pragma unroll
                for (int j = 0; j < 4; j++)
                    wmma::mma_sync(c[i][j], af[i], bf[j], c[i][j]);
        }
    }

    __syncthreads();
#pragma unroll
    for (int i = 0; i < 2; i++)
#pragma unroll
        for (int j = 0; j < 4; j++)
            wmma::store_matrix_sync(Cs + (wm * 32 + i * 16) * (BN + 4) + wn * 64 + j * 16,
                                    c[i][j], BN + 4, wmma::mem_row_major);
    __syncthreads();

#pragma unroll
    for (int i = 0; i < 16; i++) {
        int idx4 = tid + i * 256;
        int r    = idx4 >> 5;
        int c4   = (idx4 & 31) * 4;
        float4 v = *reinterpret_cast<const float4*>(Cs + r * (BN + 4) + c4);
        if (bias) {
            float4 bv = *reinterpret_cast<const float4*>(bias + bn + c4);
            v.x += bv.x; v.y += bv.y; v.z += bv.z; v.w += bv.w;
        }
        if (act == 1) {
            v.x = fmaxf(v.x, 0.f); v.y = fmaxf(v.y, 0.f);
            v.z = fmaxf(v.z, 0.f); v.w = fmaxf(v.w, 0.f);
        }
        int gr = bm + r;
        if (lpart) {
            float4 wv4 = *reinterpret_cast<const float4*>(lw + bn + c4);
            float d = v.x * wv4.x + v.y * wv4.y + v.z * wv4.z + v.w * wv4.w;
#pragma unroll
            for (int o = 16; o > 0; o >>= 1)
                d += __shfl_xor_sync(0xffffffffu, d, o);
            if ((tid & 31) == 0)
                lpart[(size_t)(bn >> 7) * M + gr] = d;
        } else if (gate_tile) {
            int b_, t_;
            if (gate_tile == 1) { b_ = gr >> 8; t_ = gr & 255; }
            else                { b_ = gr;      t_ = 0; }
            int col = bn + c4;
            int g   = col >> 10;
            int h   = col & 1023;
            int nt_ = h >> 4;
            int nl_ = h & 15;
            size_t dst = ((((size_t)t_ * 64 + nt_) * 3 + g) * 256 + b_) * 16 + nl_;
            *reinterpret_cast<float4*>(C + dst) = v;
        } else {
            *reinterpret_cast<float4*>(C + (size_t)gr * ldc + bn + c4) = v;
        }
    }
}

__global__ void logits_reduce(const float* __restrict__ lpart,
                              const float* __restrict__ b2,
                              float* __restrict__ logits)
{
    int i = blockIdx.x * blockDim.x + threadIdx.x;
    if (i >= BT) return;
    logits[i] = lpart[i] + lpart[BT + i] + lpart[2 * BT + i] +
                lpart[3 * BT + i] + b2[0];
}

// ----------------------------------------------------------------------------
// Whh pre-swizzle (unchanged)
// ----------------------------------------------------------------------------
__global__ void swizzle_whh(const float* __restrict__ whh, float* __restrict__ wsw)
{
    int nt = blockIdx.x;
    int n0 = nt * 16;
    for (int i = threadIdx.x; i < 128 * 6 * 32; i += blockDim.x) {
        int lane  = i & 31;
        int pos   = i >> 5;
        int kstep = pos / 6;
        int g2    = pos % 6;
        int g  = g2 >> 1;
        int nj = g2 & 1;
        int q = lane >> 2, t = lane & 3;
        const float* src = whh + (size_t)(g * H + n0 + nj * 8 + q) * H + kstep * 8 + t;
        float2 v;
        v.x = __uint_as_float(f2tf32(src[0]));
        v.y = __uint_as_float(f2tf32(src[4]));
        *reinterpret_cast<float2*>(wsw + (size_t)nt * WSW_TILE + (size_t)pos * 64 + lane * 2) = v;
    }
}

// ----------------------------------------------------------------------------
// Fused single GRU step v8: gi in gate-tile layout [nt][3][256][16]
// (per-t block stride = B*H3). Everything else = proven v7.
// ----------------------------------------------------------------------------
constexpr int RC_LDA     = 20;
constexpr int RC_GFLOATS = 3 * 128 * RC_LDA;
constexpr int RC_SMEM_BYTES = RC_GFLOATS * 4;

__global__ void __launch_bounds__(512, 1)
gru_step(const float* __restrict__ wsw, const float* __restrict__ bhh,
         const float* __restrict__ gi,
         const float* __restrict__ hF_read, float* __restrict__ hF_write,
         float* __restrict__ eout_t, size_t eout_bstride,
         float* __restrict__ hrow_write)
{
    extern __shared__ float Gsm[];

    const int tid  = threadIdx.x;
    const int lane = tid & 31;
    const int w    = tid >> 5;
    const int grp  = w >> 2;
    const int wm   = w & 3;
    const int nt   = blockIdx.x & 63;
    const int bt   = blockIdx.x >> 6;
    const int b0   = bt * 128;
    const int n0   = nt * 16;

    const float2* wg  = reinterpret_cast<const float2*>(wsw + (size_t)nt * WSW_TILE);
    const float4* hF4 = reinterpret_cast<const float4*>(hF_read);
    const int k8base  = grp * 32;
    const int mbb     = bt * 8 + wm * 2;

    float acc[2][3][2][4];
#pragma unroll
    for (int mh = 0; mh < 2; mh++)
#pragma unroll
        for (int g = 0; g < 3; g++)
#pragma unroll
            for (int nj = 0; nj < 2; nj++)
#pragma unroll
                for (int e = 0; e < 4; e++) acc[mh][g][nj][e] = 0.f;

    float4 pf[2];
    float2 wv[6];
#pragma unroll
    for (int mh = 0; mh < 2; mh++)
        pf[mh] = hF4[((size_t)k8base * 16 + mbb + mh) * 32 + lane];
#pragma unroll
    for (int j = 0; j < 6; j++)
        wv[j] = wg[((size_t)(k8base * 6) + j) * 32 + lane];

    for (int c = 0; c < 32; c++) {
        uint32_t A[2][4];
#pragma unroll
        for (int mh = 0; mh < 2; mh++) {
            A[mh][0] = f2tf32(pf[mh].x);
            A[mh][1] = f2tf32(pf[mh].y);
            A[mh][2] = f2tf32(pf[mh].z);
            A[mh][3] = f2tf32(pf[mh].w);
        }
        uint32_t bw0[6], bw1[6];
#pragma unroll
        for (int j = 0; j < 6; j++) {
            bw0[j] = __float_as_uint(wv[j].x);
            bw1[j] = __float_as_uint(wv[j].y);
        }

        if (c < 31) {
#pragma unroll
            for (int mh = 0; mh < 2; mh++)
                pf[mh] = hF4[((size_t)(k8base + c + 1) * 16 + mbb + mh) * 32 + lane];
#pragma unroll
            for (int j = 0; j < 6; j++)
                wv[j] = wg[((size_t)((k8base + c + 1) * 6) + j) * 32 + lane];
        }

#pragma unroll
        for (int g = 0; g < 3; g++) {
#pragma unroll
            for (int nj = 0; nj < 2; nj++) {
                int j = g * 2 + nj;
                mma_tf32(acc[0][g][nj], A[0], bw0[j], bw1[j]);
                mma_tf32(acc[1][g][nj], A[1], bw0[j], bw1[j]);
            }
        }
    }

    const int q = lane >> 2;
    const int t = lane & 3;
    const int ccol = 2 * t;
#pragma unroll
    for (int pass = 3; pass >= 0; pass--) {
        if (grp == pass) {
#pragma unroll
            for (int mh = 0; mh < 2; mh++)
#pragma unroll
                for (int g = 0; g < 3; g++)
#pragma unroll
                    for (int nj = 0; nj < 2; nj++) {
                        int row = wm * 32 + mh * 16 + q;
                        float* b0p = Gsm + (g * 128 + row) * RC_LDA + nj * 8 + ccol;
                        float* b1p = Gsm + (g * 128 + row + 8) * RC_LDA + nj * 8 + ccol;
                        if (pass == 3) {
                            b0p[0] = acc[mh][g][nj][0];
                            b0p[1] = acc[mh][g][nj][1];
                            b1p[0] = acc[mh][g][nj][2];
                            b1p[1] = acc[mh][g][nj][3];
                        } else {
                            b0p[0] += acc[mh][g][nj][0];
                            b0p[1] += acc[mh][g][nj][1];
                            b1p[0] += acc[mh][g][nj][2];
                            b1p[1] += acc[mh][g][nj][3];
                        }
                    }
        }
        __syncthreads();
    }

    {
        const int k8l  = tid >> 8;
        const int mbl  = (tid >> 5) & 7;
        const int ln   = tid & 31;
        const int bq   = ln >> 2;
        const int nq   = ln & 3;
        const size_t fidx = ((size_t)(nt * 2 + k8l) * 16 + (bt * 8 + mbl)) * 32 + ln;
        const float* gt0 = gi + (size_t)(nt * 3 + 0) * 4096;
        const float* gt1 = gi + (size_t)(nt * 3 + 1) * 4096;
        const float* gt2 = gi + (size_t)(nt * 3 + 2) * 4096;

        float4 hv4 = hF4[fidx];
        float outv[4];
#pragma unroll
        for (int kh = 0; kh < 2; kh++) {
#pragma unroll
            for (int rh = 0; rh < 2; rh++) {
                int reg = rh + 2 * kh;
                int bl  = mbl * 16 + bq + 8 * rh;
                int nl  = k8l * 8 + nq + 4 * kh;
                int b   = b0 + bl;
                int nc  = n0 + nl;
                float hr = Gsm[(0 * 128 + bl) * RC_LDA + nl] + bhh[nc];
                float hz = Gsm[(1 * 128 + bl) * RC_LDA + nl] + bhh[H + nc];
                float hn = Gsm[(2 * 128 + bl) * RC_LDA + nl] + bhh[2 * H + nc];
                float ir  = gt0[b * 16 + nl];
                float iz  = gt1[b * 16 + nl];
                float in_ = gt2[b * 16 + nl];
                float r  = sigf(ir + hr);
                float z  = sigf(iz + hz);
                float nn = tanhf(in_ + r * hn);
                float hv = (&hv4.x)[reg];
                float hnew = (1.f - z) * nn + z * hv;
                outv[reg] = hnew;
                if (eout_t) eout_t[(size_t)b * eout_bstride + nc] = hnew;
                if (hrow_write) hrow_write[(size_t)b * H + nc] = hnew;
            }
        }
        float4 o4 = make_float4(outv[0], outv[1], outv[2], outv[3]);
        reinterpret_cast<float4*>(hF_write)[fidx] = o4;
    }
}

// ----------------------------------------------------------------------------
// Small kernels
// ----------------------------------------------------------------------------
__global__ void softmax_kernel(const float* __restrict__ logits,
                               float* __restrict__ wts)
{
    __shared__ float sdata[T];
    int b = blockIdx.x, t = threadIdx.x;
    float v = logits[t * B + b];
    sdata[t] = v;
    __syncthreads();
    for (int s = T / 2; s > 0; s >>= 1) {
        if (t < s) sdata[t] = fmaxf(sdata[t], sdata[t + s]);
        __syncthreads();
    }
    float mx = sdata[0];
    __syncthreads();
    float e = expf(v - mx);
    sdata[t] = e;
    __syncthreads();
    for (int s = T / 2; s > 0; s >>= 1) {
        if (t < s) sdata[t] += sdata[t + s];
        __syncthreads();
    }
    wts[t * B + b] = e / sdata[0];
}

__global__ void pool_kernel(const float* __restrict__ eout,
                            const float* __restrict__ wts,
                            float* __restrict__ hsF,
                            float* __restrict__ rep_out)
{
    __shared__ float w[T];
    int b = blockIdx.x, tid = threadIdx.x;
    w[tid] = wts[tid * B + b];
    __syncthreads();
    for (int h0 = tid; h0 < H; h0 += blockDim.x) {
        const float* base = eout + (size_t)b * H + h0;
        float acc = 0.f;
#pragma unroll 4
        for (int t = 0; t < T; t++) acc += w[t] * base[(size_t)t * B * H];
        hsF[hf_idx(b, h0)] = acc;
        if (rep_out) rep_out[b * H + h0] = acc;
    }
}

__global__ void gather_last(const float* __restrict__ x, float* __restrict__ p0)
{
    int idx = blockIdx.x * blockDim.x + threadIdx.x;
    if (idx >= B * D) return;
    int b = idx / D, dd = idx % D;
    p0[idx] = x[((size_t)b * T + (T - 1)) * D + dd];
}

// fp32 pred head (proven)
__global__ void pred_kernel(const float* __restrict__ l1,
                            const float* __restrict__ w,
                            const float* __restrict__ bias,
                            float* __restrict__ out, int ldc)
{
    __shared__ float row[HID];
    int m = blockIdx.x;
    for (int k = threadIdx.x; k < HID; k += blockDim.x)
        row[k] = l1[(size_t)m * HID + k];
    __syncthreads();
    int n = threadIdx.x;
    if (n < D) {
        const float* wr = w + (size_t)n * HID;
        float acc = bias[n];
        for (int k = 0; k < HID; k++) acc += row[k] * wr[k];
        out[(size_t)m * ldc + n] = acc;
    }
}

// ----------------------------------------------------------------------------
// Host driver
// ----------------------------------------------------------------------------
static inline void launch_gemm(const float* A, int lda, const float* W,
                               const float* bias, float* C, int ldc,
                               int M, int N, int K, int act, int gate_tile = 0,
                               const float* lw = nullptr, float* lpart = nullptr)
{
    dim3 grid(N / BN, M / BM);
    gemm_tf32_v3<<<grid, 256, GM_SMEM_BYTES>>>(A, lda, W, bias, C, ldc, M, N, K,
                                               act, gate_tile, lw, lpart);
}

extern "C" void kernel_launch(void* const* d_in, const int* in_sizes, int n_in,
                              void* d_out, int out_size)
{
    const float* x       = (const float*)d_in[0];
    const float* p2l_w1  = (const float*)d_in[2];
    const float* p2l_b1  = (const float*)d_in[3];
    const float* p2l_w2  = (const float*)d_in[4];
    const float* p2l_b2  = (const float*)d_in[5];
    const float* enc_wih = (const float*)d_in[6];
    const float* enc_whh = (const float*)d_in[7];
    const float* enc_bih = (const float*)d_in[8];
    const float* enc_bhh = (const float*)d_in[9];
    const float* dec_wih = (const float*)d_in[10];
    const float* dec_whh = (const float*)d_in[11];
    const float* dec_bih = (const float*)d_in[12];
    const float* dec_bhh = (const float*)d_in[13];
    const float* l2p_w1  = (const float*)d_in[14];
    const float* l2p_b1  = (const float*)d_in[15];
    const float* l2p_w2  = (const float*)d_in[16];
    const float* l2p_b2  = (const float*)d_in[17];
    const float* l2s_w1  = (const float*)d_in[18];
    const float* l2s_b1  = (const float*)d_in[19];
    const float* l2s_w2  = (const float*)d_in[20];
    const float* l2s_b2  = (const float*)d_in[21];

    float* out = (float*)d_out;
    const int PREDS = B * P * D;
    float* rep_out = (out_size >= PREDS + B * H) ? (out + PREDS) : nullptr;

    float *p_buf1, *p_latent, *p_xp, *p_eout, *p_hb0, *p_hb1, *p_logits,
          *p_lpart, *p_wts, *p_hs, *p_hs2, *p_hrow, *p_p0, *p_d1, *p_dinp,
          *p_gi, *p_l1, *p_wsw_enc, *p_wsw_dec, *p_wtf;
    void* tmp;
#define SYM(dst, sym) cudaGetSymbolAddress(&tmp, sym); dst = (decltype(dst))tmp;
    SYM(p_buf1, g_buf1)   SYM(p_latent, g_latent) SYM(p_xp, g_xp)
    SYM(p_eout, g_eout)   SYM(p_hb0, g_hb0)       SYM(p_hb1, g_hb1)
    SYM(p_logits, g_logits) SYM(p_lpart, g_lpart) SYM(p_wts, g_wts)
    SYM(p_hs, g_hs)       SYM(p_hs2, g_hs2)       SYM(p_hrow, g_hrow)
    SYM(p_p0, g_p0)       SYM(p_d1, g_d1)         SYM(p_dinp, g_dinp)
    SYM(p_gi, g_gi)       SYM(p_l1, g_l1)         SYM(p_wsw_enc, g_wsw_enc)
    SYM(p_wsw_dec, g_wsw_dec) SYM(p_wtf, g_wtf)
#undef SYM

    float* w_p2l1   = p_wtf + WT_P2L1;
    float* w_p2l2   = p_wtf + WT_P2L2;
    float* w_encwih = p_wtf + WT_ENCWIH;
    float* w_l2s1   = p_wtf + WT_L2S1;
    float* w_decwih = p_wtf + WT_DECWIH;
    float* w_l2p1   = p_wtf + WT_L2P1;

    cudaFuncSetAttribute(gru_step, cudaFuncAttributeMaxDynamicSharedMemorySize,
                         RC_SMEM_BYTES);
    cudaFuncSetAttribute(gemm_tf32_v3, cudaFuncAttributeMaxDynamicSharedMemorySize,
                         GM_SMEM_BYTES);

    // ---- one-time weight preprocessing (3 launches; ncu -s 5 -> xp GEMM) ----
    swizzle_whh<<<64, 256>>>(enc_whh, p_wsw_enc);
    swizzle_whh<<<64, 256>>>(dec_whh, p_wsw_dec);
    cvt_all<<<(CN5 + 255) / 256, 256>>>(p2l_w1, p2l_w2, enc_wih, l2s_w1,
                                        dec_wih, l2p_w1, p_wtf);

    // ---- par2lat(x) ----
    launch_gemm(x, D, w_p2l1, p2l_b1, p_buf1, HID, BT, HID, D, 1);
    launch_gemm(p_buf1, HID, w_p2l2, p2l_b2, p_latent, H, BT, H, HID, 1);

    // ---- xp = latent @ enc_wih^T + enc_bih, gate-tile layout ----
    launch_gemm(p_latent, H, w_encwih, enc_bih, p_xp, H3, BT, H3, H, 0, 1);

    // ---- encoder recurrence ----
    cudaMemsetAsync(p_hb0, 0, (size_t)B * H * sizeof(float));
    {
        float* hr = p_hb0;
        float* hw = p_hb1;
        for (int t = 0; t < T; t++) {
            gru_step<<<128, 512, RC_SMEM_BYTES>>>(
                p_wsw_enc, enc_bhh,
                p_xp + (size_t)t * B * H3,
                hr, hw,
                p_eout + (size_t)t * B * H, (size_t)H,
                nullptr);
            float* t2 = hr; hr = hw; hw = t2;
        }
    }

    // ---- attention pooling: fused s1-GEMM + logits dot ----
    launch_gemm(p_eout, H, w_l2s1, l2s_b1, nullptr, HID, BT, HID, H, 1, 0,
                l2s_w2, p_lpart);
    logits_reduce<<<BT / 256, 256>>>(p_lpart, l2s_b2, p_logits);
    softmax_kernel<<<B, T>>>(p_logits, p_wts);
    pool_kernel<<<B, 256>>>(p_eout, p_wts, p_hs, rep_out);

    // ---- autoregressive decode ----
    gather_last<<<(B * D + 255) / 256, 256>>>(x, p_p0);
    float* hF_read  = p_hs;
    float* hF_write = p_hs2;
    for (int s = 0; s < P; s++) {
        const float* pin = (s == 0) ? p_p0 : (out + (size_t)(s - 1) * D);
        int plda = (s == 0) ? D : (P * D);
        launch_gemm(pin, plda, w_p2l1, p2l_b1, p_d1, HID, B, HID, D, 1);
        launch_gemm(p_d1, HID, w_p2l2, p2l_b2, p_dinp, H, B, H, HID, 1);
        launch_gemm(p_dinp, H, w_decwih, dec_bih, p_gi, H3, B, H3, H, 0, 2);
        gru_step<<<128, 512, RC_SMEM_BYTES>>>(
            p_wsw_dec, dec_bhh, p_gi,
            hF_read, hF_write, nullptr, 0, p_hrow);
        launch_gemm(p_hrow, H, w_l2p1, l2p_b1, p_l1, HID, B, HID, H, 1);
        pred_kernel<<<B, 128>>>(p_l1, l2p_w2, l2p_b2,
                                out + (size_t)s * D, P * D);
        float* t2 = hF_read; hF_read = hF_write; hF_write = t2;
    }
}